// round 1
// baseline (speedup 1.0000x reference)
#include <cuda_runtime.h>

#define B_ 4
#define T_ 2048
#define C_ 1024
#define H_ 16
#define D_ 64
#define M_ (B_*T_)   /* 8192 */

// Scratch (static device globals — allocation rules forbid cudaMalloc)
__device__ float g_q[(size_t)B_*H_*T_*D_];
__device__ float g_k[(size_t)B_*H_*T_*D_];
__device__ float g_v[(size_t)B_*H_*T_*D_];
__device__ float g_y[(size_t)M_*C_];

// ---------------------------------------------------------------------------
// QKV GEMM: qkv = x @ w_attn + b_attn, scattered into Q/K/V as [B,H,T,D]
// 128x128 tile, K-step 8, 256 threads, 8x8 microtile per thread.
// ---------------------------------------------------------------------------
__global__ __launch_bounds__(256) void qkv_gemm_kernel(
    const float* __restrict__ X, const float* __restrict__ W,
    const float* __restrict__ bias)
{
    const int K = C_, N = 3 * C_;
    __shared__ float As[8][128];
    __shared__ float Bs[8][128];

    const int tid = threadIdx.x;
    const int tx = tid & 15, ty = tid >> 4;
    const int row0 = blockIdx.y * 128, col0 = blockIdx.x * 128;

    float acc[8][8];
#pragma unroll
    for (int i = 0; i < 8; i++)
#pragma unroll
        for (int j = 0; j < 8; j++) acc[i][j] = 0.f;

    const int arow = tid >> 1;        // 0..127
    const int akk  = (tid & 1) * 4;   // 0 or 4
    const int brow = tid >> 5;        // 0..7
    const int bcol = (tid & 31) * 4;  // 0..124

    for (int k0 = 0; k0 < K; k0 += 8) {
        float4 a = *(const float4*)&X[(size_t)(row0 + arow) * K + k0 + akk];
        As[akk + 0][arow] = a.x;
        As[akk + 1][arow] = a.y;
        As[akk + 2][arow] = a.z;
        As[akk + 3][arow] = a.w;
        *(float4*)&Bs[brow][bcol] =
            *(const float4*)&W[(size_t)(k0 + brow) * N + col0 + bcol];
        __syncthreads();
#pragma unroll
        for (int kk = 0; kk < 8; kk++) {
            float ar[8], br[8];
#pragma unroll
            for (int i = 0; i < 8; i++) ar[i] = As[kk][ty * 8 + i];
#pragma unroll
            for (int j = 0; j < 8; j++) br[j] = Bs[kk][tx * 8 + j];
#pragma unroll
            for (int i = 0; i < 8; i++)
#pragma unroll
                for (int j = 0; j < 8; j++) acc[i][j] += ar[i] * br[j];
        }
        __syncthreads();
    }

    // Epilogue: n0..n0+7 stay within one head (8 | 64) and one of q/k/v.
    const int n0 = col0 + tx * 8;
    const int which = n0 / C_;
    const int c0 = n0 % C_;
    const int h = c0 / D_;
    const int d0 = c0 % D_;
    float* dst = (which == 0) ? g_q : (which == 1) ? g_k : g_v;

    float bj[8];
#pragma unroll
    for (int j = 0; j < 8; j++) bj[j] = bias[n0 + j];

#pragma unroll
    for (int i = 0; i < 8; i++) {
        int m = row0 + ty * 8 + i;
        int b = m / T_, t = m % T_;
        float* p = &dst[(((size_t)(b * H_ + h)) * T_ + t) * D_ + d0];
        float4 v0 = make_float4(acc[i][0] + bj[0], acc[i][1] + bj[1],
                                acc[i][2] + bj[2], acc[i][3] + bj[3]);
        float4 v1 = make_float4(acc[i][4] + bj[4], acc[i][5] + bj[5],
                                acc[i][6] + bj[6], acc[i][7] + bj[7]);
        *(float4*)p = v0;
        *(float4*)(p + 4) = v1;
    }
}

// ---------------------------------------------------------------------------
// Flash attention (causal, online softmax).
// One thread = one q row: q[64], o[64] in regs; K/V rows broadcast from smem.
// Scores parked in smem (conflict-free [j][tid]) to avoid register blowup.
// ---------------------------------------------------------------------------
#define BQ 128
#define TK 32

__global__ __launch_bounds__(128) void attn_kernel()
{
    __shared__ float sK[TK][D_];    // 8 KB
    __shared__ float sV[TK][D_];    // 8 KB
    __shared__ float sS[TK][BQ];    // 16 KB

    const int b = blockIdx.z, h = blockIdx.y;
    const int q0 = blockIdx.x * BQ;
    const int q_idx = q0 + threadIdx.x;
    const size_t head_base = ((size_t)(b * H_ + h)) * T_;

    float q[D_], o[D_];
    {
        const float4* qp = (const float4*)&g_q[(head_base + q_idx) * D_];
#pragma unroll
        for (int d4 = 0; d4 < 16; d4++) {
            float4 v = qp[d4];
            q[4 * d4 + 0] = v.x; q[4 * d4 + 1] = v.y;
            q[4 * d4 + 2] = v.z; q[4 * d4 + 3] = v.w;
        }
    }
#pragma unroll
    for (int d = 0; d < D_; d++) o[d] = 0.f;

    float mrun = -1e30f, lrun = 0.f;
    const float scale = 0.125f;  // 1/sqrt(64)
    const int kend = q0 + BQ;    // causal: k <= q

    for (int k0 = 0; k0 < kend; k0 += TK) {
        __syncthreads();  // protect previous tile reads before overwrite
        for (int idx = threadIdx.x; idx < TK * D_ / 4; idx += BQ) {
            int j = idx >> 4;
            int d4 = (idx & 15) * 4;
            *(float4*)&sK[j][d4] =
                *(const float4*)&g_k[(head_base + k0 + j) * D_ + d4];
            *(float4*)&sV[j][d4] =
                *(const float4*)&g_v[(head_base + k0 + j) * D_ + d4];
        }
        __syncthreads();

        // Phase A: scores for this tile (4 partial sums break FMA RAW chain)
        float tmax = -1e30f;
#pragma unroll 1
        for (int j = 0; j < TK; j++) {
            const float4* kr = (const float4*)&sK[j][0];
            float s0 = 0.f, s1 = 0.f, s2 = 0.f, s3 = 0.f;
#pragma unroll
            for (int d4 = 0; d4 < 16; d4++) {
                float4 kv = kr[d4];
                s0 += q[4 * d4 + 0] * kv.x;
                s1 += q[4 * d4 + 1] * kv.y;
                s2 += q[4 * d4 + 2] * kv.z;
                s3 += q[4 * d4 + 3] * kv.w;
            }
            float s = ((s0 + s1) + (s2 + s3)) * scale;
            if (k0 + j > q_idx) s = -1e30f;  // causal mask
            sS[j][threadIdx.x] = s;
            tmax = fmaxf(tmax, s);
        }

        // Online softmax rescale (once per tile)
        float mnew = fmaxf(mrun, tmax);
        float corr = __expf(mrun - mnew);
        mrun = mnew;
        lrun *= corr;
#pragma unroll
        for (int d = 0; d < D_; d++) o[d] *= corr;

        // Phase B: accumulate p @ V
#pragma unroll 1
        for (int j = 0; j < TK; j++) {
            float p = __expf(sS[j][threadIdx.x] - mrun);
            lrun += p;
            const float4* vr = (const float4*)&sV[j][0];
#pragma unroll
            for (int d4 = 0; d4 < 16; d4++) {
                float4 vv = vr[d4];
                o[4 * d4 + 0] += p * vv.x;
                o[4 * d4 + 1] += p * vv.y;
                o[4 * d4 + 2] += p * vv.z;
                o[4 * d4 + 3] += p * vv.w;
            }
        }
    }

    // Normalize, write back to [B,T,C] layout
    float inv = 1.f / lrun;
    float* yp = &g_y[((size_t)(b * T_ + q_idx)) * C_ + h * D_];
#pragma unroll
    for (int d4 = 0; d4 < 16; d4++) {
        float4 v = make_float4(o[4 * d4 + 0] * inv, o[4 * d4 + 1] * inv,
                               o[4 * d4 + 2] * inv, o[4 * d4 + 3] * inv);
        ((float4*)yp)[d4] = v;
    }
}

// ---------------------------------------------------------------------------
// Proj GEMM: out = y @ w_proj + b_proj
// ---------------------------------------------------------------------------
__global__ __launch_bounds__(256) void proj_gemm_kernel(
    const float* __restrict__ W, const float* __restrict__ bias,
    float* __restrict__ out)
{
    const int K = C_, N = C_;
    __shared__ float As[8][128];
    __shared__ float Bs[8][128];

    const int tid = threadIdx.x;
    const int tx = tid & 15, ty = tid >> 4;
    const int row0 = blockIdx.y * 128, col0 = blockIdx.x * 128;

    float acc[8][8];
#pragma unroll
    for (int i = 0; i < 8; i++)
#pragma unroll
        for (int j = 0; j < 8; j++) acc[i][j] = 0.f;

    const int arow = tid >> 1;
    const int akk  = (tid & 1) * 4;
    const int brow = tid >> 5;
    const int bcol = (tid & 31) * 4;

    for (int k0 = 0; k0 < K; k0 += 8) {
        float4 a = *(const float4*)&g_y[(size_t)(row0 + arow) * K + k0 + akk];
        As[akk + 0][arow] = a.x;
        As[akk + 1][arow] = a.y;
        As[akk + 2][arow] = a.z;
        As[akk + 3][arow] = a.w;
        *(float4*)&Bs[brow][bcol] =
            *(const float4*)&W[(size_t)(k0 + brow) * N + col0 + bcol];
        __syncthreads();
#pragma unroll
        for (int kk = 0; kk < 8; kk++) {
            float ar[8], br[8];
#pragma unroll
            for (int i = 0; i < 8; i++) ar[i] = As[kk][ty * 8 + i];
#pragma unroll
            for (int j = 0; j < 8; j++) br[j] = Bs[kk][tx * 8 + j];
#pragma unroll
            for (int i = 0; i < 8; i++)
#pragma unroll
                for (int j = 0; j < 8; j++) acc[i][j] += ar[i] * br[j];
        }
        __syncthreads();
    }

    const int n0 = col0 + tx * 8;
    float bj[8];
#pragma unroll
    for (int j = 0; j < 8; j++) bj[j] = bias[n0 + j];

#pragma unroll
    for (int i = 0; i < 8; i++) {
        int m = row0 + ty * 8 + i;
        float* p = &out[(size_t)m * N + n0];
        float4 v0 = make_float4(acc[i][0] + bj[0], acc[i][1] + bj[1],
                                acc[i][2] + bj[2], acc[i][3] + bj[3]);
        float4 v1 = make_float4(acc[i][4] + bj[4], acc[i][5] + bj[5],
                                acc[i][6] + bj[6], acc[i][7] + bj[7]);
        *(float4*)p = v0;
        *(float4*)(p + 4) = v1;
    }
}

// ---------------------------------------------------------------------------
extern "C" void kernel_launch(void* const* d_in, const int* in_sizes, int n_in,
                              void* d_out, int out_size)
{
    const float* x      = (const float*)d_in[0];
    const float* w_attn = (const float*)d_in[1];
    const float* b_attn = (const float*)d_in[2];
    const float* w_proj = (const float*)d_in[3];
    const float* b_proj = (const float*)d_in[4];
    float* out = (float*)d_out;

    dim3 g1(3 * C_ / 128, M_ / 128);   // (24, 64)
    qkv_gemm_kernel<<<g1, 256>>>(x, w_attn, b_attn);

    dim3 g2(T_ / BQ, H_, B_);          // (16, 16, 4)
    attn_kernel<<<g2, 128>>>();

    dim3 g3(C_ / 128, M_ / 128);       // (8, 64)
    proj_gemm_kernel<<<g3, 256>>>(w_proj, b_proj, out);
}

// round 2
// speedup vs baseline: 1.4297x; 1.4297x over previous
#include <cuda_runtime.h>
#include <cuda_bf16.h>
#include <cstdint>

#define B_ 4
#define T_ 2048
#define C_ 1024
#define H_ 16
#define D_ 64
#define M_ (B_*T_)   /* 8192 */

// ---------------- device scratch (no cudaMalloc allowed) --------------------
__device__ float g_q[(size_t)M_*C_];
__device__ float g_k[(size_t)M_*C_];
__device__ float g_v[(size_t)M_*C_];
__device__ __nv_bfloat16 g_xh[(size_t)M_*C_];
__device__ __nv_bfloat16 g_xl[(size_t)M_*C_];
__device__ __nv_bfloat16 g_wah[(size_t)C_*3*C_];
__device__ __nv_bfloat16 g_wal[(size_t)C_*3*C_];
__device__ __nv_bfloat16 g_wph[(size_t)C_*C_];
__device__ __nv_bfloat16 g_wpl[(size_t)C_*C_];
__device__ __nv_bfloat16 g_yh[(size_t)M_*C_];
__device__ __nv_bfloat16 g_yl[(size_t)M_*C_];

// ---------------- fp32 -> bf16 hi/lo split ----------------------------------
template<int WHICH>  // 0: x, 1: w_attn, 2: w_proj
__global__ void split_bf16_kernel(const float* __restrict__ src, int n4)
{
    __nv_bfloat16* hi = (WHICH == 0) ? g_xh : (WHICH == 1) ? g_wah : g_wph;
    __nv_bfloat16* lo = (WHICH == 0) ? g_xl : (WHICH == 1) ? g_wal : g_wpl;
    int i = blockIdx.x * blockDim.x + threadIdx.x;
    if (i >= n4) return;
    float4 v = ((const float4*)src)[i];
    float s[4] = {v.x, v.y, v.z, v.w};
    uint32_t hp[2], lp[2];
#pragma unroll
    for (int p = 0; p < 2; p++) {
        __nv_bfloat16 h0 = __float2bfloat16(s[2*p]);
        __nv_bfloat16 h1 = __float2bfloat16(s[2*p+1]);
        __nv_bfloat16 l0 = __float2bfloat16(s[2*p]   - __bfloat162float(h0));
        __nv_bfloat16 l1 = __float2bfloat16(s[2*p+1] - __bfloat162float(h1));
        hp[p] = (uint32_t)__bfloat16_as_ushort(h0) |
                ((uint32_t)__bfloat16_as_ushort(h1) << 16);
        lp[p] = (uint32_t)__bfloat16_as_ushort(l0) |
                ((uint32_t)__bfloat16_as_ushort(l1) << 16);
    }
    ((uint2*)hi)[i] = make_uint2(hp[0], hp[1]);
    ((uint2*)lo)[i] = make_uint2(lp[0], lp[1]);
}

// ---------------- mma / ldmatrix / cp.async helpers --------------------------
__device__ __forceinline__ uint32_t s2u(const void* p) {
    return (uint32_t)__cvta_generic_to_shared(p);
}
__device__ __forceinline__ void cpa16(uint32_t dst, const void* src) {
    asm volatile("cp.async.cg.shared.global [%0], [%1], 16;" :: "r"(dst), "l"(src));
}
#define CP_COMMIT() asm volatile("cp.async.commit_group;" ::: "memory")
#define CP_WAIT1()  asm volatile("cp.async.wait_group 1;" ::: "memory")
#define CP_WAIT0()  asm volatile("cp.async.wait_group 0;" ::: "memory")

#define LDM_X4(r, addr) \
    asm volatile("ldmatrix.sync.aligned.m8n8.x4.shared.b16 {%0,%1,%2,%3},[%4];" \
        : "=r"((r)[0]), "=r"((r)[1]), "=r"((r)[2]), "=r"((r)[3]) : "r"(addr))
#define LDM_X4T(r, addr) \
    asm volatile("ldmatrix.sync.aligned.m8n8.x4.trans.shared.b16 {%0,%1,%2,%3},[%4];" \
        : "=r"((r)[0]), "=r"((r)[1]), "=r"((r)[2]), "=r"((r)[3]) : "r"(addr))

#define MMA16816(d, a, b) \
    asm volatile("mma.sync.aligned.m16n8k16.row.col.f32.bf16.bf16.f32 " \
        "{%0,%1,%2,%3},{%4,%5,%6,%7},{%8,%9},{%0,%1,%2,%3};" \
        : "+f"((d)[0]), "+f"((d)[1]), "+f"((d)[2]), "+f"((d)[3]) \
        : "r"((a)[0]), "r"((a)[1]), "r"((a)[2]), "r"((a)[3]), \
          "r"((b)[0]), "r"((b)[1]))

// ---------------- split-bf16 3-product GEMM ---------------------------------
// C[M x N] = A[M x 1024] * B[1024 x N] + bias, A = Ah+Al, B = Bh+Bl (bf16).
// Block 128x128, BK=16, 256 thr (8 warps 2x4), warp 64x32, double-buffered.
#define BM 128
#define BN 128
#define BK 16
#define AST 24    /* smem A row pitch, bf16 units (48B)  */
#define BST 136   /* smem B row pitch, bf16 units (272B) */
#define KTILES (C_/BK)

template<bool SCATTER>   // true: qkv (scatter to g_q/g_k/g_v), false: proj
__global__ __launch_bounds__(256) void gemm_splitbf16(
    const float* __restrict__ bias, float* __restrict__ out, int N)
{
    __shared__ __nv_bfloat16 sAh[2][BM*AST];
    __shared__ __nv_bfloat16 sAl[2][BM*AST];
    __shared__ __nv_bfloat16 sBh[2][BK*BST];
    __shared__ __nv_bfloat16 sBl[2][BK*BST];

    const __nv_bfloat16* Agh = SCATTER ? g_xh : g_yh;
    const __nv_bfloat16* Agl = SCATTER ? g_xl : g_yl;
    const __nv_bfloat16* Bgh = SCATTER ? g_wah : g_wph;
    const __nv_bfloat16* Bgl = SCATTER ? g_wal : g_wpl;

    const int K = C_;
    const int tid  = threadIdx.x;
    const int lane = tid & 31, wid = tid >> 5;
    const int wr = wid >> 2, wc = wid & 3;
    const int row0 = blockIdx.y * BM, col0 = blockIdx.x * BN;

    // global-load assignment
    const int rA = tid >> 1, cA = tid & 1;    // A: 128 rows x 2 chunks
    const int rB = tid >> 4, cB = tid & 15;   // B: 16 rows x 16 chunks

    const __nv_bfloat16* srcAh = Agh + (size_t)(row0 + rA) * K + cA * 8;
    const __nv_bfloat16* srcAl = Agl + (size_t)(row0 + rA) * K + cA * 8;
    const __nv_bfloat16* srcBh = Bgh + (size_t)rB * N + col0 + cB * 8;
    const __nv_bfloat16* srcBl = Bgl + (size_t)rB * N + col0 + cB * 8;

    const uint32_t dAh0 = s2u(&sAh[0][rA*AST + cA*8]);
    const uint32_t dAh1 = s2u(&sAh[1][rA*AST + cA*8]);
    const uint32_t dAl0 = s2u(&sAl[0][rA*AST + cA*8]);
    const uint32_t dAl1 = s2u(&sAl[1][rA*AST + cA*8]);
    const uint32_t dBh0 = s2u(&sBh[0][rB*BST + cB*8]);
    const uint32_t dBh1 = s2u(&sBh[1][rB*BST + cB*8]);
    const uint32_t dBl0 = s2u(&sBl[0][rB*BST + cB*8]);
    const uint32_t dBl1 = s2u(&sBl[1][rB*BST + cB*8]);

    auto load_stage = [&](int kt, uint32_t dah, uint32_t dal,
                          uint32_t dbh, uint32_t dbl) {
        cpa16(dah, srcAh + kt * BK);
        cpa16(dal, srcAl + kt * BK);
        cpa16(dbh, srcBh + (size_t)kt * BK * N);
        cpa16(dbl, srcBl + (size_t)kt * BK * N);
    };

    // ldmatrix lane addressing
    const int lm = lane & 15, lh = lane >> 4;
    const uint32_t aOff = (uint32_t)((wr*64 + lm) * AST + lh * 8) * 2;
    const uint32_t bOff = (uint32_t)(lm * BST + (wc*32 + lh*8)) * 2;
    const uint32_t aH0 = s2u(sAh[0]) + aOff, aH1 = s2u(sAh[1]) + aOff;
    const uint32_t aL0 = s2u(sAl[0]) + aOff, aL1 = s2u(sAl[1]) + aOff;
    const uint32_t bH0 = s2u(sBh[0]) + bOff, bH1 = s2u(sBh[1]) + bOff;
    const uint32_t bL0 = s2u(sBl[0]) + bOff, bL1 = s2u(sBl[1]) + bOff;

    float acc[4][4][4];
#pragma unroll
    for (int mi = 0; mi < 4; mi++)
#pragma unroll
        for (int ni = 0; ni < 4; ni++)
#pragma unroll
            for (int r = 0; r < 4; r++) acc[mi][ni][r] = 0.f;

    auto compute = [&](uint32_t aH, uint32_t aL, uint32_t bH, uint32_t bL) {
        uint32_t ah[4][4], al[4][4], bb[4][2], r[4];
#pragma unroll
        for (int mi = 0; mi < 4; mi++) LDM_X4(ah[mi], aH + mi * (16*AST*2));
        LDM_X4T(r, bH);      bb[0][0]=r[0]; bb[0][1]=r[1]; bb[1][0]=r[2]; bb[1][1]=r[3];
        LDM_X4T(r, bH + 32); bb[2][0]=r[0]; bb[2][1]=r[1]; bb[3][0]=r[2]; bb[3][1]=r[3];
#pragma unroll
        for (int mi = 0; mi < 4; mi++)
#pragma unroll
            for (int ni = 0; ni < 4; ni++) MMA16816(acc[mi][ni], ah[mi], bb[ni]);
#pragma unroll
        for (int mi = 0; mi < 4; mi++) LDM_X4(al[mi], aL + mi * (16*AST*2));
#pragma unroll
        for (int mi = 0; mi < 4; mi++)
#pragma unroll
            for (int ni = 0; ni < 4; ni++) MMA16816(acc[mi][ni], al[mi], bb[ni]);
        LDM_X4T(r, bL);      bb[0][0]=r[0]; bb[0][1]=r[1]; bb[1][0]=r[2]; bb[1][1]=r[3];
        LDM_X4T(r, bL + 32); bb[2][0]=r[0]; bb[2][1]=r[1]; bb[3][0]=r[2]; bb[3][1]=r[3];
#pragma unroll
        for (int mi = 0; mi < 4; mi++)
#pragma unroll
            for (int ni = 0; ni < 4; ni++) MMA16816(acc[mi][ni], ah[mi], bb[ni]);
    };

    load_stage(0, dAh0, dAl0, dBh0, dBl0);
    CP_COMMIT();

#pragma unroll 1
    for (int kt = 0; kt < KTILES; kt += 2) {
        load_stage(kt + 1, dAh1, dAl1, dBh1, dBl1);
        CP_COMMIT();
        CP_WAIT1();
        __syncthreads();
        compute(aH0, aL0, bH0, bL0);
        __syncthreads();
        if (kt + 2 < KTILES) {
            load_stage(kt + 2, dAh0, dAl0, dBh0, dBl0);
            CP_COMMIT();
            CP_WAIT1();
        } else {
            CP_WAIT0();
        }
        __syncthreads();
        compute(aH1, aL1, bH1, bL1);
        __syncthreads();
    }

    // ---------------- epilogue ----------------
#pragma unroll
    for (int ni = 0; ni < 4; ni++) {
        const int n = col0 + wc*32 + ni*8 + (lane & 3) * 2;
        const float b0 = bias[n], b1 = bias[n + 1];
        if (SCATTER) {
            const int which = n / C_;
            const int c0 = n % C_;
            const int h = c0 / D_, d0 = c0 % D_;
            float* dst = (which == 0) ? g_q : (which == 1) ? g_k : g_v;
#pragma unroll
            for (int mi = 0; mi < 4; mi++) {
                const int m = row0 + wr*64 + mi*16 + (lane >> 2);
                const int b = m / T_, t = m % T_;
                const size_t base = (((size_t)(b*H_ + h)) * T_ + t) * D_ + d0;
                *(float2*)&dst[base] =
                    make_float2(acc[mi][ni][0] + b0, acc[mi][ni][1] + b1);
                *(float2*)&dst[base + 8*D_] =
                    make_float2(acc[mi][ni][2] + b0, acc[mi][ni][3] + b1);
            }
        } else {
#pragma unroll
            for (int mi = 0; mi < 4; mi++) {
                const int m = row0 + wr*64 + mi*16 + (lane >> 2);
                *(float2*)&out[(size_t)m * N + n] =
                    make_float2(acc[mi][ni][0] + b0, acc[mi][ni][1] + b1);
                *(float2*)&out[(size_t)(m + 8) * N + n] =
                    make_float2(acc[mi][ni][2] + b0, acc[mi][ni][3] + b1);
            }
        }
    }
}

// ---------------- flash attention (fp32 SIMT, unchanged math) ----------------
#define BQ 128
#define TK 32

__global__ __launch_bounds__(128) void attn_kernel()
{
    __shared__ float sK[TK][D_];
    __shared__ float sV[TK][D_];
    __shared__ float sS[TK][BQ];

    const int b = blockIdx.z, h = blockIdx.y;
    const int q0 = blockIdx.x * BQ;
    const int q_idx = q0 + threadIdx.x;
    const size_t head_base = ((size_t)(b * H_ + h)) * T_;

    float q[D_], o[D_];
    {
        const float4* qp = (const float4*)&g_q[(head_base + q_idx) * D_];
#pragma unroll
        for (int d4 = 0; d4 < 16; d4++) {
            float4 v = qp[d4];
            q[4*d4+0] = v.x; q[4*d4+1] = v.y; q[4*d4+2] = v.z; q[4*d4+3] = v.w;
        }
    }
#pragma unroll
    for (int d = 0; d < D_; d++) o[d] = 0.f;

    float mrun = -1e30f, lrun = 0.f;
    const float scale = 0.125f;
    const int kend = q0 + BQ;

    for (int k0 = 0; k0 < kend; k0 += TK) {
        __syncthreads();
        for (int idx = threadIdx.x; idx < TK * D_ / 4; idx += BQ) {
            int j = idx >> 4;
            int d4 = (idx & 15) * 4;
            *(float4*)&sK[j][d4] = *(const float4*)&g_k[(head_base + k0 + j) * D_ + d4];
            *(float4*)&sV[j][d4] = *(const float4*)&g_v[(head_base + k0 + j) * D_ + d4];
        }
        __syncthreads();

        float tmax = -1e30f;
#pragma unroll 1
        for (int j = 0; j < TK; j++) {
            const float4* kr = (const float4*)&sK[j][0];
            float s0 = 0.f, s1 = 0.f, s2 = 0.f, s3 = 0.f;
#pragma unroll
            for (int d4 = 0; d4 < 16; d4++) {
                float4 kv = kr[d4];
                s0 += q[4*d4+0] * kv.x;
                s1 += q[4*d4+1] * kv.y;
                s2 += q[4*d4+2] * kv.z;
                s3 += q[4*d4+3] * kv.w;
            }
            float s = ((s0 + s1) + (s2 + s3)) * scale;
            if (k0 + j > q_idx) s = -1e30f;
            sS[j][threadIdx.x] = s;
            tmax = fmaxf(tmax, s);
        }

        float mnew = fmaxf(mrun, tmax);
        float corr = __expf(mrun - mnew);
        mrun = mnew;
        lrun *= corr;
#pragma unroll
        for (int d = 0; d < D_; d++) o[d] *= corr;

#pragma unroll 1
        for (int j = 0; j < TK; j++) {
            float p = __expf(sS[j][threadIdx.x] - mrun);
            lrun += p;
            const float4* vr = (const float4*)&sV[j][0];
#pragma unroll
            for (int d4 = 0; d4 < 16; d4++) {
                float4 vv = vr[d4];
                o[4*d4+0] += p * vv.x;
                o[4*d4+1] += p * vv.y;
                o[4*d4+2] += p * vv.z;
                o[4*d4+3] += p * vv.w;
            }
        }
    }

    // write y as bf16 hi/lo split (proj GEMM input)
    const float inv = 1.f / lrun;
    const size_t ybase = ((size_t)(b * T_ + q_idx)) * C_ + h * D_;
#pragma unroll
    for (int d2 = 0; d2 < 32; d2++) {
        float v0 = o[2*d2] * inv, v1 = o[2*d2+1] * inv;
        __nv_bfloat16 h0 = __float2bfloat16(v0);
        __nv_bfloat16 h1 = __float2bfloat16(v1);
        __nv_bfloat16 l0 = __float2bfloat16(v0 - __bfloat162float(h0));
        __nv_bfloat16 l1 = __float2bfloat16(v1 - __bfloat162float(h1));
        __nv_bfloat162 hv; hv.x = h0; hv.y = h1;
        __nv_bfloat162 lv; lv.x = l0; lv.y = l1;
        ((__nv_bfloat162*)&g_yh[ybase])[d2] = hv;
        ((__nv_bfloat162*)&g_yl[ybase])[d2] = lv;
    }
}

// -----------------------------------------------------------------------------
extern "C" void kernel_launch(void* const* d_in, const int* in_sizes, int n_in,
                              void* d_out, int out_size)
{
    const float* x      = (const float*)d_in[0];
    const float* w_attn = (const float*)d_in[1];
    const float* b_attn = (const float*)d_in[2];
    const float* w_proj = (const float*)d_in[3];
    const float* b_proj = (const float*)d_in[4];
    float* out = (float*)d_out;

    // fp32 -> bf16 hi/lo splits
    {
        int n4 = M_ * C_ / 4;
        split_bf16_kernel<0><<<(n4 + 255) / 256, 256>>>(x, n4);
    }
    {
        int n4 = C_ * 3 * C_ / 4;
        split_bf16_kernel<1><<<(n4 + 255) / 256, 256>>>(w_attn, n4);
    }
    {
        int n4 = C_ * C_ / 4;
        split_bf16_kernel<2><<<(n4 + 255) / 256, 256>>>(w_proj, n4);
    }

    // QKV GEMM (tensor cores, scatter to [B,H,T,D])
    dim3 g1(3 * C_ / BN, M_ / BM);   // (24, 64)
    gemm_splitbf16<true><<<g1, 256>>>(b_attn, nullptr, 3 * C_);

    // attention
    dim3 g2(T_ / BQ, H_, B_);        // (16, 16, 4)
    attn_kernel<<<g2, 128>>>();

    // proj GEMM
    dim3 g3(C_ / BN, M_ / BM);       // (8, 64)
    gemm_splitbf16<false><<<g3, 256>>>(b_proj, out, C_);
}

// round 3
// speedup vs baseline: 2.8830x; 2.0164x over previous
#include <cuda_runtime.h>
#include <cuda_bf16.h>
#include <cstdint>

#define B_ 4
#define T_ 2048
#define C_ 1024
#define H_ 16
#define D_ 64
#define M_ (B_*T_)   /* 8192 */

// ---------------- device scratch ---------------------------------------------
__device__ __nv_bfloat16 g_xh[(size_t)M_*C_];
__device__ __nv_bfloat16 g_xl[(size_t)M_*C_];
__device__ __nv_bfloat16 g_wah[(size_t)C_*3*C_];
__device__ __nv_bfloat16 g_wal[(size_t)C_*3*C_];
__device__ __nv_bfloat16 g_wph[(size_t)C_*C_];
__device__ __nv_bfloat16 g_wpl[(size_t)C_*C_];
__device__ __nv_bfloat16 g_yh[(size_t)M_*C_];
__device__ __nv_bfloat16 g_yl[(size_t)M_*C_];
// q/k/v split bf16, [B,H,T,D]
__device__ __nv_bfloat16 g_qh[(size_t)M_*C_];
__device__ __nv_bfloat16 g_ql[(size_t)M_*C_];
__device__ __nv_bfloat16 g_kh[(size_t)M_*C_];
__device__ __nv_bfloat16 g_kl[(size_t)M_*C_];
__device__ __nv_bfloat16 g_vh[(size_t)M_*C_];
__device__ __nv_bfloat16 g_vl[(size_t)M_*C_];

// ---------------- fp32 -> bf16 hi/lo split ------------------------------------
template<int WHICH>
__global__ void split_bf16_kernel(const float* __restrict__ src, int n4)
{
    __nv_bfloat16* hi = (WHICH == 0) ? g_xh : (WHICH == 1) ? g_wah : g_wph;
    __nv_bfloat16* lo = (WHICH == 0) ? g_xl : (WHICH == 1) ? g_wal : g_wpl;
    int i = blockIdx.x * blockDim.x + threadIdx.x;
    if (i >= n4) return;
    float4 v = ((const float4*)src)[i];
    float s[4] = {v.x, v.y, v.z, v.w};
    uint32_t hp[2], lp[2];
#pragma unroll
    for (int p = 0; p < 2; p++) {
        __nv_bfloat16 h0 = __float2bfloat16(s[2*p]);
        __nv_bfloat16 h1 = __float2bfloat16(s[2*p+1]);
        __nv_bfloat16 l0 = __float2bfloat16(s[2*p]   - __bfloat162float(h0));
        __nv_bfloat16 l1 = __float2bfloat16(s[2*p+1] - __bfloat162float(h1));
        hp[p] = (uint32_t)__bfloat16_as_ushort(h0) |
                ((uint32_t)__bfloat16_as_ushort(h1) << 16);
        lp[p] = (uint32_t)__bfloat16_as_ushort(l0) |
                ((uint32_t)__bfloat16_as_ushort(l1) << 16);
    }
    ((uint2*)hi)[i] = make_uint2(hp[0], hp[1]);
    ((uint2*)lo)[i] = make_uint2(lp[0], lp[1]);
}

// ---------------- helpers ------------------------------------------------------
__device__ __forceinline__ uint32_t s2u(const void* p) {
    return (uint32_t)__cvta_generic_to_shared(p);
}
__device__ __forceinline__ void cpa16(uint32_t dst, const void* src) {
    asm volatile("cp.async.cg.shared.global [%0], [%1], 16;" :: "r"(dst), "l"(src));
}
#define CP_COMMIT() asm volatile("cp.async.commit_group;" ::: "memory")
#define CP_WAIT1()  asm volatile("cp.async.wait_group 1;" ::: "memory")
#define CP_WAIT0()  asm volatile("cp.async.wait_group 0;" ::: "memory")

#define LDM_X4(r, addr) \
    asm volatile("ldmatrix.sync.aligned.m8n8.x4.shared.b16 {%0,%1,%2,%3},[%4];" \
        : "=r"((r)[0]), "=r"((r)[1]), "=r"((r)[2]), "=r"((r)[3]) : "r"(addr))
#define LDM_X4T(r, addr) \
    asm volatile("ldmatrix.sync.aligned.m8n8.x4.trans.shared.b16 {%0,%1,%2,%3},[%4];" \
        : "=r"((r)[0]), "=r"((r)[1]), "=r"((r)[2]), "=r"((r)[3]) : "r"(addr))

#define MMA16816(d, a, b) \
    asm volatile("mma.sync.aligned.m16n8k16.row.col.f32.bf16.bf16.f32 " \
        "{%0,%1,%2,%3},{%4,%5,%6,%7},{%8,%9},{%0,%1,%2,%3};" \
        : "+f"((d)[0]), "+f"((d)[1]), "+f"((d)[2]), "+f"((d)[3]) \
        : "r"((a)[0]), "r"((a)[1]), "r"((a)[2]), "r"((a)[3]), \
          "r"((b)[0]), "r"((b)[1]))

__device__ __forceinline__ void store_split2(
    __nv_bfloat16* ph, __nv_bfloat16* pl, float a, float b)
{
    __nv_bfloat16 ha = __float2bfloat16(a);
    __nv_bfloat16 hb = __float2bfloat16(b);
    __nv_bfloat16 la = __float2bfloat16(a - __bfloat162float(ha));
    __nv_bfloat16 lb = __float2bfloat16(b - __bfloat162float(hb));
    __nv_bfloat162 hv; hv.x = ha; hv.y = hb;
    __nv_bfloat162 lv; lv.x = la; lv.y = lb;
    *(__nv_bfloat162*)ph = hv;
    *(__nv_bfloat162*)pl = lv;
}
__device__ __forceinline__ uint32_t pack_hi(float a, float b) {
    __nv_bfloat162 v; v.x = __float2bfloat16(a); v.y = __float2bfloat16(b);
    return *(uint32_t*)&v;
}
__device__ __forceinline__ uint32_t pack_lo(float a, float b) {
    __nv_bfloat16 ha = __float2bfloat16(a), hb = __float2bfloat16(b);
    __nv_bfloat162 v;
    v.x = __float2bfloat16(a - __bfloat162float(ha));
    v.y = __float2bfloat16(b - __bfloat162float(hb));
    return *(uint32_t*)&v;
}

// ---------------- split-bf16 3-product GEMM -----------------------------------
#define BM 128
#define BN 128
#define BK 16
#define AST 24
#define BST 136
#define KTILES (C_/BK)

template<bool SCATTER>
__global__ __launch_bounds__(256) void gemm_splitbf16(
    const float* __restrict__ bias, float* __restrict__ out, int N)
{
    __shared__ __nv_bfloat16 sAh[2][BM*AST];
    __shared__ __nv_bfloat16 sAl[2][BM*AST];
    __shared__ __nv_bfloat16 sBh[2][BK*BST];
    __shared__ __nv_bfloat16 sBl[2][BK*BST];

    const __nv_bfloat16* Agh = SCATTER ? g_xh : g_yh;
    const __nv_bfloat16* Agl = SCATTER ? g_xl : g_yl;
    const __nv_bfloat16* Bgh = SCATTER ? g_wah : g_wph;
    const __nv_bfloat16* Bgl = SCATTER ? g_wal : g_wpl;

    const int K = C_;
    const int tid  = threadIdx.x;
    const int lane = tid & 31, wid = tid >> 5;
    const int wr = wid >> 2, wc = wid & 3;
    const int row0 = blockIdx.y * BM, col0 = blockIdx.x * BN;

    const int rA = tid >> 1, cA = tid & 1;
    const int rB = tid >> 4, cB = tid & 15;

    const __nv_bfloat16* srcAh = Agh + (size_t)(row0 + rA) * K + cA * 8;
    const __nv_bfloat16* srcAl = Agl + (size_t)(row0 + rA) * K + cA * 8;
    const __nv_bfloat16* srcBh = Bgh + (size_t)rB * N + col0 + cB * 8;
    const __nv_bfloat16* srcBl = Bgl + (size_t)rB * N + col0 + cB * 8;

    const uint32_t dAh0 = s2u(&sAh[0][rA*AST + cA*8]);
    const uint32_t dAh1 = s2u(&sAh[1][rA*AST + cA*8]);
    const uint32_t dAl0 = s2u(&sAl[0][rA*AST + cA*8]);
    const uint32_t dAl1 = s2u(&sAl[1][rA*AST + cA*8]);
    const uint32_t dBh0 = s2u(&sBh[0][rB*BST + cB*8]);
    const uint32_t dBh1 = s2u(&sBh[1][rB*BST + cB*8]);
    const uint32_t dBl0 = s2u(&sBl[0][rB*BST + cB*8]);
    const uint32_t dBl1 = s2u(&sBl[1][rB*BST + cB*8]);

    auto load_stage = [&](int kt, uint32_t dah, uint32_t dal,
                          uint32_t dbh, uint32_t dbl) {
        cpa16(dah, srcAh + kt * BK);
        cpa16(dal, srcAl + kt * BK);
        cpa16(dbh, srcBh + (size_t)kt * BK * N);
        cpa16(dbl, srcBl + (size_t)kt * BK * N);
    };

    const int lm = lane & 15, lh = lane >> 4;
    const uint32_t aOff = (uint32_t)((wr*64 + lm) * AST + lh * 8) * 2;
    const uint32_t bOff = (uint32_t)(lm * BST + (wc*32 + lh*8)) * 2;
    const uint32_t aH0 = s2u(sAh[0]) + aOff, aH1 = s2u(sAh[1]) + aOff;
    const uint32_t aL0 = s2u(sAl[0]) + aOff, aL1 = s2u(sAl[1]) + aOff;
    const uint32_t bH0 = s2u(sBh[0]) + bOff, bH1 = s2u(sBh[1]) + bOff;
    const uint32_t bL0 = s2u(sBl[0]) + bOff, bL1 = s2u(sBl[1]) + bOff;

    float acc[4][4][4];
#pragma unroll
    for (int mi = 0; mi < 4; mi++)
#pragma unroll
        for (int ni = 0; ni < 4; ni++)
#pragma unroll
            for (int r = 0; r < 4; r++) acc[mi][ni][r] = 0.f;

    auto compute = [&](uint32_t aH, uint32_t aL, uint32_t bH, uint32_t bL) {
        uint32_t ah[4][4], al[4][4], bb[4][2], r[4];
#pragma unroll
        for (int mi = 0; mi < 4; mi++) LDM_X4(ah[mi], aH + mi * (16*AST*2));
        LDM_X4T(r, bH);      bb[0][0]=r[0]; bb[0][1]=r[1]; bb[1][0]=r[2]; bb[1][1]=r[3];
        LDM_X4T(r, bH + 32); bb[2][0]=r[0]; bb[2][1]=r[1]; bb[3][0]=r[2]; bb[3][1]=r[3];
#pragma unroll
        for (int mi = 0; mi < 4; mi++)
#pragma unroll
            for (int ni = 0; ni < 4; ni++) MMA16816(acc[mi][ni], ah[mi], bb[ni]);
#pragma unroll
        for (int mi = 0; mi < 4; mi++) LDM_X4(al[mi], aL + mi * (16*AST*2));
#pragma unroll
        for (int mi = 0; mi < 4; mi++)
#pragma unroll
            for (int ni = 0; ni < 4; ni++) MMA16816(acc[mi][ni], al[mi], bb[ni]);
        LDM_X4T(r, bL);      bb[0][0]=r[0]; bb[0][1]=r[1]; bb[1][0]=r[2]; bb[1][1]=r[3];
        LDM_X4T(r, bL + 32); bb[2][0]=r[0]; bb[2][1]=r[1]; bb[3][0]=r[2]; bb[3][1]=r[3];
#pragma unroll
        for (int mi = 0; mi < 4; mi++)
#pragma unroll
            for (int ni = 0; ni < 4; ni++) MMA16816(acc[mi][ni], ah[mi], bb[ni]);
    };

    load_stage(0, dAh0, dAl0, dBh0, dBl0);
    CP_COMMIT();

#pragma unroll 1
    for (int kt = 0; kt < KTILES; kt += 2) {
        load_stage(kt + 1, dAh1, dAl1, dBh1, dBl1);
        CP_COMMIT();
        CP_WAIT1();
        __syncthreads();
        compute(aH0, aL0, bH0, bL0);
        __syncthreads();
        if (kt + 2 < KTILES) {
            load_stage(kt + 2, dAh0, dAl0, dBh0, dBl0);
            CP_COMMIT();
            CP_WAIT1();
        } else {
            CP_WAIT0();
        }
        __syncthreads();
        compute(aH1, aL1, bH1, bL1);
        __syncthreads();
    }

    // ---------------- epilogue ----------------
#pragma unroll
    for (int ni = 0; ni < 4; ni++) {
        const int n = col0 + wc*32 + ni*8 + (lane & 3) * 2;
        const float b0 = bias[n], b1 = bias[n + 1];
        if (SCATTER) {
            const int which = n / C_;
            const int c0 = n % C_;
            const int h = c0 / D_, d0 = c0 % D_;
            const float sc = (which == 0) ? 0.125f : 1.0f;  // fold 1/sqrt(D) into q
            __nv_bfloat16* dh = (which == 0) ? g_qh : (which == 1) ? g_kh : g_vh;
            __nv_bfloat16* dl = (which == 0) ? g_ql : (which == 1) ? g_kl : g_vl;
#pragma unroll
            for (int mi = 0; mi < 4; mi++) {
                const int m = row0 + wr*64 + mi*16 + (lane >> 2);
                const int b = m / T_, t = m % T_;
                const size_t base = (((size_t)(b*H_ + h)) * T_ + t) * D_ + d0;
                store_split2(&dh[base], &dl[base],
                             (acc[mi][ni][0] + b0) * sc, (acc[mi][ni][1] + b1) * sc);
                store_split2(&dh[base + 8*D_], &dl[base + 8*D_],
                             (acc[mi][ni][2] + b0) * sc, (acc[mi][ni][3] + b1) * sc);
            }
        } else {
#pragma unroll
            for (int mi = 0; mi < 4; mi++) {
                const int m = row0 + wr*64 + mi*16 + (lane >> 2);
                *(float2*)&out[(size_t)m * N + n] =
                    make_float2(acc[mi][ni][0] + b0, acc[mi][ni][1] + b1);
                *(float2*)&out[(size_t)(m + 8) * N + n] =
                    make_float2(acc[mi][ni][2] + b0, acc[mi][ni][3] + b1);
            }
        }
    }
}

// ---------------- tensor-core flash attention ---------------------------------
// CTA: 128 q rows, 8 warps (16 q each). k-tile = 64. All operands split bf16.
#define ATT_PITCH 72

__global__ __launch_bounds__(256) void attn_mma_kernel()
{
    __shared__ __nv_bfloat16 sm[4 * 64 * ATT_PITCH];  // KH | KL | VH | VL (36.9KB)
    __nv_bfloat16* sKH = sm;
    __nv_bfloat16* sKL = sm + 64*ATT_PITCH;
    __nv_bfloat16* sVH = sm + 2*64*ATT_PITCH;
    __nv_bfloat16* sVL = sm + 3*64*ATT_PITCH;

    const int b = blockIdx.z, h = blockIdx.y;
    const int q0 = blockIdx.x * 128;
    const int tid = threadIdx.x, lane = tid & 31, wid = tid >> 5;
    const size_t hb = ((size_t)(b*H_ + h)) * T_ * D_;

    // ---- stage Q tile (128x64 hi/lo) through smem, ldmatrix to regs ----
    {
        const int row = tid >> 1, cg = (tid & 1) * 32;
        const uint4* s4h = (const uint4*)(g_qh + hb + (size_t)(q0+row)*D_ + cg);
        const uint4* s4l = (const uint4*)(g_ql + hb + (size_t)(q0+row)*D_ + cg);
        uint4* d4h = (uint4*)(sm + row*ATT_PITCH + cg);
        uint4* d4l = (uint4*)(sm + 2*64*ATT_PITCH + row*ATT_PITCH + cg);
#pragma unroll
        for (int i = 0; i < 4; i++) { d4h[i] = s4h[i]; d4l[i] = s4l[i]; }
    }
    __syncthreads();

    uint32_t qh[4][4], ql[4][4];
    {
        const int qr = lane & 15, qc = (lane & 16) >> 1;
        const uint32_t baseH = s2u(sm) +
            (uint32_t)((wid*16 + qr)*ATT_PITCH + qc) * 2;
        const uint32_t baseL = baseH + (uint32_t)(2*64*ATT_PITCH*2);
#pragma unroll
        for (int kk = 0; kk < 4; kk++) {
            LDM_X4(qh[kk], baseH + kk * 32);
            LDM_X4(ql[kk], baseL + kk * 32);
        }
    }
    __syncthreads();

    float o[8][4];
#pragma unroll
    for (int n = 0; n < 8; n++)
#pragma unroll
        for (int r = 0; r < 4; r++) o[n][r] = 0.f;
    float m0 = -1e30f, m1 = -1e30f, l0 = 0.f, l1 = 0.f;

    // fragment addressing
    const int kbrow = (lane & 7) + ((lane & 16) >> 1);  // K b-frag (non-trans)
    const int kbcol = (lane & 8);
    const int vrow  = lane & 15;                        // V b-frag (trans)
    const int vcolg = (lane & 16) >> 1;
    const uint32_t kAddrH = s2u(sKH) + (uint32_t)(kbrow*ATT_PITCH + kbcol) * 2;
    const uint32_t kAddrL = s2u(sKL) + (uint32_t)(kbrow*ATT_PITCH + kbcol) * 2;
    const uint32_t vAddrH = s2u(sVH) + (uint32_t)(vrow*ATT_PITCH + vcolg) * 2;
    const uint32_t vAddrL = s2u(sVL) + (uint32_t)(vrow*ATT_PITCH + vcolg) * 2;

    // cp.async assignment for K/V tiles
    const int kvr = tid >> 3, kvc = (tid & 7) * 8;
    const uint32_t dKH = s2u(sKH + kvr*ATT_PITCH + kvc);
    const uint32_t dKL = s2u(sKL + kvr*ATT_PITCH + kvc);
    const uint32_t dVH = s2u(sVH + kvr*ATT_PITCH + kvc);
    const uint32_t dVL = s2u(sVL + kvr*ATT_PITCH + kvc);
    const uint32_t rstep = 32*ATT_PITCH*2;

    const int row_lo = q0 + wid*16 + (lane >> 2);  // this thread's q rows
    const int ntiles = q0/64 + 2;

#pragma unroll 1
    for (int t = 0; t < ntiles; t++) {
        const int k0 = t * 64;
        // load K/V tile (hi/lo)
        {
            const size_t g = hb + (size_t)(k0 + kvr)*D_ + kvc;
            cpa16(dKH, g_kh + g);  cpa16(dKH + rstep, g_kh + g + 32*D_);
            cpa16(dKL, g_kl + g);  cpa16(dKL + rstep, g_kl + g + 32*D_);
            cpa16(dVH, g_vh + g);  cpa16(dVH + rstep, g_vh + g + 32*D_);
            cpa16(dVL, g_vl + g);  cpa16(dVL + rstep, g_vl + g + 32*D_);
        }
        CP_COMMIT();
        CP_WAIT0();
        __syncthreads();

        // ---- S = Q K^T (3 products) ----
        float s[8][4];
#pragma unroll
        for (int n = 0; n < 8; n++)
#pragma unroll
            for (int r = 0; r < 4; r++) s[n][r] = 0.f;

#pragma unroll
        for (int kk = 0; kk < 4; kk++) {
            uint32_t kf[4][4];
#pragma unroll
            for (int np = 0; np < 4; np++)
                LDM_X4(kf[np], kAddrH + (uint32_t)(np*16*ATT_PITCH)*2 + kk*32);
#pragma unroll
            for (int np = 0; np < 4; np++) {
                MMA16816(s[2*np],   qh[kk], kf[np]);
                MMA16816(s[2*np+1], qh[kk], kf[np]+2);
            }
#pragma unroll
            for (int np = 0; np < 4; np++) {
                MMA16816(s[2*np],   ql[kk], kf[np]);
                MMA16816(s[2*np+1], ql[kk], kf[np]+2);
            }
#pragma unroll
            for (int np = 0; np < 4; np++)
                LDM_X4(kf[np], kAddrL + (uint32_t)(np*16*ATT_PITCH)*2 + kk*32);
#pragma unroll
            for (int np = 0; np < 4; np++) {
                MMA16816(s[2*np],   qh[kk], kf[np]);
                MMA16816(s[2*np+1], qh[kk], kf[np]+2);
            }
        }

        // ---- causal mask (diagonal tiles only) ----
        if (k0 + 64 > q0) {
#pragma unroll
            for (int n = 0; n < 8; n++) {
                const int c = k0 + n*8 + 2*(lane & 3);
                if (c     > row_lo)     s[n][0] = -1e30f;
                if (c + 1 > row_lo)     s[n][1] = -1e30f;
                if (c     > row_lo + 8) s[n][2] = -1e30f;
                if (c + 1 > row_lo + 8) s[n][3] = -1e30f;
            }
        }

        // ---- online softmax ----
        float tm0 = -1e30f, tm1 = -1e30f;
#pragma unroll
        for (int n = 0; n < 8; n++) {
            tm0 = fmaxf(tm0, fmaxf(s[n][0], s[n][1]));
            tm1 = fmaxf(tm1, fmaxf(s[n][2], s[n][3]));
        }
        tm0 = fmaxf(tm0, __shfl_xor_sync(0xffffffff, tm0, 1));
        tm0 = fmaxf(tm0, __shfl_xor_sync(0xffffffff, tm0, 2));
        tm1 = fmaxf(tm1, __shfl_xor_sync(0xffffffff, tm1, 1));
        tm1 = fmaxf(tm1, __shfl_xor_sync(0xffffffff, tm1, 2));

        const float mn0 = fmaxf(m0, tm0), mn1 = fmaxf(m1, tm1);
        const float c0 = __expf(m0 - mn0), c1 = __expf(m1 - mn1);
        m0 = mn0; m1 = mn1;
#pragma unroll
        for (int n = 0; n < 8; n++) {
            o[n][0] *= c0; o[n][1] *= c0; o[n][2] *= c1; o[n][3] *= c1;
        }

        float ls0 = 0.f, ls1 = 0.f;
#pragma unroll
        for (int n = 0; n < 8; n++) {
            s[n][0] = __expf(s[n][0] - m0);
            s[n][1] = __expf(s[n][1] - m0);
            s[n][2] = __expf(s[n][2] - m1);
            s[n][3] = __expf(s[n][3] - m1);
            ls0 += s[n][0] + s[n][1];
            ls1 += s[n][2] + s[n][3];
        }
        ls0 += __shfl_xor_sync(0xffffffff, ls0, 1);
        ls0 += __shfl_xor_sync(0xffffffff, ls0, 2);
        ls1 += __shfl_xor_sync(0xffffffff, ls1, 1);
        ls1 += __shfl_xor_sync(0xffffffff, ls1, 2);
        l0 = l0 * c0 + ls0;
        l1 = l1 * c1 + ls1;

        // ---- pack P to split bf16 a-frags ----
        uint32_t pah[4][4], pal[4][4];
#pragma unroll
        for (int j = 0; j < 4; j++) {
            pah[j][0] = pack_hi(s[2*j][0],   s[2*j][1]);
            pah[j][1] = pack_hi(s[2*j][2],   s[2*j][3]);
            pah[j][2] = pack_hi(s[2*j+1][0], s[2*j+1][1]);
            pah[j][3] = pack_hi(s[2*j+1][2], s[2*j+1][3]);
            pal[j][0] = pack_lo(s[2*j][0],   s[2*j][1]);
            pal[j][1] = pack_lo(s[2*j][2],   s[2*j][3]);
            pal[j][2] = pack_lo(s[2*j+1][0], s[2*j+1][1]);
            pal[j][3] = pack_lo(s[2*j+1][2], s[2*j+1][3]);
        }

        // ---- O += P V (3 products) ----
#pragma unroll
        for (int kk = 0; kk < 4; kk++) {
            uint32_t vf[4][4];
#pragma unroll
            for (int nc = 0; nc < 4; nc++)
                LDM_X4T(vf[nc], vAddrH + (uint32_t)(kk*16*ATT_PITCH)*2 + nc*32);
#pragma unroll
            for (int nc = 0; nc < 4; nc++) {
                MMA16816(o[2*nc],   pah[kk], vf[nc]);
                MMA16816(o[2*nc+1], pah[kk], vf[nc]+2);
            }
#pragma unroll
            for (int nc = 0; nc < 4; nc++) {
                MMA16816(o[2*nc],   pal[kk], vf[nc]);
                MMA16816(o[2*nc+1], pal[kk], vf[nc]+2);
            }
#pragma unroll
            for (int nc = 0; nc < 4; nc++)
                LDM_X4T(vf[nc], vAddrL + (uint32_t)(kk*16*ATT_PITCH)*2 + nc*32);
#pragma unroll
            for (int nc = 0; nc < 4; nc++) {
                MMA16816(o[2*nc],   pah[kk], vf[nc]);
                MMA16816(o[2*nc+1], pah[kk], vf[nc]+2);
            }
        }
        __syncthreads();  // done reading tile before next overwrite
    }

    // ---- epilogue: y (split bf16) ----
    const float inv0 = 1.f / l0, inv1 = 1.f / l1;
    const int r0 = row_lo, r1 = row_lo + 8;
#pragma unroll
    for (int n = 0; n < 8; n++) {
        const int d = n*8 + 2*(lane & 3);
        const size_t y0 = ((size_t)(b*T_ + r0))*C_ + h*D_ + d;
        const size_t y1 = ((size_t)(b*T_ + r1))*C_ + h*D_ + d;
        store_split2(&g_yh[y0], &g_yl[y0], o[n][0]*inv0, o[n][1]*inv0);
        store_split2(&g_yh[y1], &g_yl[y1], o[n][2]*inv1, o[n][3]*inv1);
    }
}

// -------------------------------------------------------------------------------
extern "C" void kernel_launch(void* const* d_in, const int* in_sizes, int n_in,
                              void* d_out, int out_size)
{
    const float* x      = (const float*)d_in[0];
    const float* w_attn = (const float*)d_in[1];
    const float* b_attn = (const float*)d_in[2];
    const float* w_proj = (const float*)d_in[3];
    const float* b_proj = (const float*)d_in[4];
    float* out = (float*)d_out;

    {
        int n4 = M_ * C_ / 4;
        split_bf16_kernel<0><<<(n4 + 255) / 256, 256>>>(x, n4);
    }
    {
        int n4 = C_ * 3 * C_ / 4;
        split_bf16_kernel<1><<<(n4 + 255) / 256, 256>>>(w_attn, n4);
    }
    {
        int n4 = C_ * C_ / 4;
        split_bf16_kernel<2><<<(n4 + 255) / 256, 256>>>(w_proj, n4);
    }

    dim3 g1(3 * C_ / BN, M_ / BM);   // (24, 64)
    gemm_splitbf16<true><<<g1, 256>>>(b_attn, nullptr, 3 * C_);

    dim3 g2(T_ / 128, H_, B_);       // (16, 16, 4)
    attn_mma_kernel<<<g2, 256>>>();

    dim3 g3(C_ / BN, M_ / BM);       // (8, 64)
    gemm_splitbf16<false><<<g3, 256>>>(b_proj, out, C_);
}

// round 5
// speedup vs baseline: 3.2021x; 1.1107x over previous
#include <cuda_runtime.h>
#include <cuda_bf16.h>
#include <cstdint>

#define B_ 4
#define T_ 2048
#define C_ 1024
#define H_ 16
#define D_ 64
#define M_ (B_*T_)   /* 8192 */

// ---------------- device scratch ---------------------------------------------
__device__ __nv_bfloat16 g_xh[(size_t)M_*C_];
__device__ __nv_bfloat16 g_xl[(size_t)M_*C_];
__device__ __nv_bfloat16 g_wah[(size_t)C_*3*C_];
__device__ __nv_bfloat16 g_wal[(size_t)C_*3*C_];
__device__ __nv_bfloat16 g_wph[(size_t)C_*C_];
__device__ __nv_bfloat16 g_wpl[(size_t)C_*C_];
__device__ __nv_bfloat16 g_yh[(size_t)M_*C_];
__device__ __nv_bfloat16 g_yl[(size_t)M_*C_];
// q/k/v split bf16, [B,H,T,D]
__device__ __nv_bfloat16 g_qh[(size_t)M_*C_];
__device__ __nv_bfloat16 g_ql[(size_t)M_*C_];
__device__ __nv_bfloat16 g_kh[(size_t)M_*C_];
__device__ __nv_bfloat16 g_kl[(size_t)M_*C_];
__device__ __nv_bfloat16 g_vh[(size_t)M_*C_];
__device__ __nv_bfloat16 g_vl[(size_t)M_*C_];

// ---------------- fp32 -> bf16 hi/lo split ------------------------------------
template<int WHICH>
__global__ void split_bf16_kernel(const float* __restrict__ src, int n4)
{
    __nv_bfloat16* hi = (WHICH == 0) ? g_xh : (WHICH == 1) ? g_wah : g_wph;
    __nv_bfloat16* lo = (WHICH == 0) ? g_xl : (WHICH == 1) ? g_wal : g_wpl;
    int i = blockIdx.x * blockDim.x + threadIdx.x;
    if (i >= n4) return;
    float4 v = ((const float4*)src)[i];
    float s[4] = {v.x, v.y, v.z, v.w};
    uint32_t hp[2], lp[2];
#pragma unroll
    for (int p = 0; p < 2; p++) {
        __nv_bfloat16 h0 = __float2bfloat16(s[2*p]);
        __nv_bfloat16 h1 = __float2bfloat16(s[2*p+1]);
        __nv_bfloat16 l0 = __float2bfloat16(s[2*p]   - __bfloat162float(h0));
        __nv_bfloat16 l1 = __float2bfloat16(s[2*p+1] - __bfloat162float(h1));
        hp[p] = (uint32_t)__bfloat16_as_ushort(h0) |
                ((uint32_t)__bfloat16_as_ushort(h1) << 16);
        lp[p] = (uint32_t)__bfloat16_as_ushort(l0) |
                ((uint32_t)__bfloat16_as_ushort(l1) << 16);
    }
    ((uint2*)hi)[i] = make_uint2(hp[0], hp[1]);
    ((uint2*)lo)[i] = make_uint2(lp[0], lp[1]);
}

// ---------------- helpers ------------------------------------------------------
__device__ __forceinline__ uint32_t s2u(const void* p) {
    return (uint32_t)__cvta_generic_to_shared(p);
}
__device__ __forceinline__ void cpa16(uint32_t dst, const void* src) {
    asm volatile("cp.async.cg.shared.global [%0], [%1], 16;" :: "r"(dst), "l"(src));
}
#define CP_COMMIT() asm volatile("cp.async.commit_group;" ::: "memory")
#define CP_WAIT0()  asm volatile("cp.async.wait_group 0;" ::: "memory")
#define CP_WAIT2()  asm volatile("cp.async.wait_group 2;" ::: "memory")

#define LDM_X4(r, addr) \
    asm volatile("ldmatrix.sync.aligned.m8n8.x4.shared.b16 {%0,%1,%2,%3},[%4];" \
        : "=r"((r)[0]), "=r"((r)[1]), "=r"((r)[2]), "=r"((r)[3]) : "r"(addr))
#define LDM_X4T(r, addr) \
    asm volatile("ldmatrix.sync.aligned.m8n8.x4.trans.shared.b16 {%0,%1,%2,%3},[%4];" \
        : "=r"((r)[0]), "=r"((r)[1]), "=r"((r)[2]), "=r"((r)[3]) : "r"(addr))

#define MMA16816(d, a, b) \
    asm volatile("mma.sync.aligned.m16n8k16.row.col.f32.bf16.bf16.f32 " \
        "{%0,%1,%2,%3},{%4,%5,%6,%7},{%8,%9},{%0,%1,%2,%3};" \
        : "+f"((d)[0]), "+f"((d)[1]), "+f"((d)[2]), "+f"((d)[3]) \
        : "r"((a)[0]), "r"((a)[1]), "r"((a)[2]), "r"((a)[3]), \
          "r"((b)[0]), "r"((b)[1]))

__device__ __forceinline__ void store_split2(
    __nv_bfloat16* ph, __nv_bfloat16* pl, float a, float b)
{
    __nv_bfloat16 ha = __float2bfloat16(a);
    __nv_bfloat16 hb = __float2bfloat16(b);
    __nv_bfloat16 la = __float2bfloat16(a - __bfloat162float(ha));
    __nv_bfloat16 lb = __float2bfloat16(b - __bfloat162float(hb));
    __nv_bfloat162 hv; hv.x = ha; hv.y = hb;
    __nv_bfloat162 lv; lv.x = la; lv.y = lb;
    *(__nv_bfloat162*)ph = hv;
    *(__nv_bfloat162*)pl = lv;
}
__device__ __forceinline__ uint32_t pack_hi(float a, float b) {
    __nv_bfloat162 v; v.x = __float2bfloat16(a); v.y = __float2bfloat16(b);
    return *(uint32_t*)&v;
}
__device__ __forceinline__ uint32_t pack_lo(float a, float b) {
    __nv_bfloat16 ha = __float2bfloat16(a), hb = __float2bfloat16(b);
    __nv_bfloat162 v;
    v.x = __float2bfloat16(a - __bfloat162float(ha));
    v.y = __float2bfloat16(b - __bfloat162float(hb));
    return *(uint32_t*)&v;
}

// ---------------- split-bf16 3-product GEMM, 4-stage pipeline ------------------
#define BM 128
#define BN 128
#define BK 16
#define AST 24    /* A smem row pitch (bf16) */
#define BST 136   /* B smem row pitch (bf16) */
#define KTILES (C_/BK)          /* 64 */
#define STAGES 4
#define ASZ (BM*AST*2)          /* 6144 B per A array */
#define BSZ (BK*BST*2)          /* 4352 B per B array */
#define STG (2*ASZ + 2*BSZ)     /* 20992 B per stage  */
#define GEMM_SMEM (STAGES*STG)  /* 83968 B */

template<bool SCATTER>
__global__ __launch_bounds__(256) void gemm_splitbf16(
    const float* __restrict__ bias, float* __restrict__ out, int N)
{
    extern __shared__ char dsm[];
    const uint32_t base = s2u(dsm);

    const __nv_bfloat16* Agh = SCATTER ? g_xh : g_yh;
    const __nv_bfloat16* Agl = SCATTER ? g_xl : g_yl;
    const __nv_bfloat16* Bgh = SCATTER ? g_wah : g_wph;
    const __nv_bfloat16* Bgl = SCATTER ? g_wal : g_wpl;

    const int K = C_;
    const int tid  = threadIdx.x;
    const int lane = tid & 31, wid = tid >> 5;
    const int wr = wid >> 2, wc = wid & 3;
    const int row0 = blockIdx.y * BM, col0 = blockIdx.x * BN;

    const int rA = tid >> 1, cA = tid & 1;
    const int rB = tid >> 4, cB = tid & 15;

    const __nv_bfloat16* srcAh = Agh + (size_t)(row0 + rA) * K + cA * 8;
    const __nv_bfloat16* srcAl = Agl + (size_t)(row0 + rA) * K + cA * 8;
    const __nv_bfloat16* srcBh = Bgh + (size_t)rB * N + col0 + cB * 8;
    const __nv_bfloat16* srcBl = Bgl + (size_t)rB * N + col0 + cB * 8;

    const uint32_t offA = (uint32_t)(rA*AST + cA*8) * 2;
    const uint32_t offB = (uint32_t)(rB*BST + cB*8) * 2;

    auto load_stage = [&](int kt, int buf) {
        const uint32_t sb = base + buf * STG;
        cpa16(sb + offA,             srcAh + kt * BK);
        cpa16(sb + ASZ + offA,       srcAl + kt * BK);
        cpa16(sb + 2*ASZ + offB,     srcBh + (size_t)kt * BK * N);
        cpa16(sb + 2*ASZ + BSZ + offB, srcBl + (size_t)kt * BK * N);
    };

    const int lm = lane & 15, lh = lane >> 4;
    const uint32_t aOff = (uint32_t)((wr*64 + lm) * AST + lh * 8) * 2;
    const uint32_t bOff = (uint32_t)(lm * BST + (wc*32 + lh*8)) * 2;

    float acc[4][4][4];
#pragma unroll
    for (int mi = 0; mi < 4; mi++)
#pragma unroll
        for (int ni = 0; ni < 4; ni++)
#pragma unroll
            for (int r = 0; r < 4; r++) acc[mi][ni][r] = 0.f;

    auto compute = [&](int buf) {
        const uint32_t sb = base + buf * STG;
        const uint32_t aH = sb + aOff;
        const uint32_t aL = sb + ASZ + aOff;
        const uint32_t bH = sb + 2*ASZ + bOff;
        const uint32_t bL = sb + 2*ASZ + BSZ + bOff;
        uint32_t ah[4][4], al[4][4], bb[4][2], r[4];
#pragma unroll
        for (int mi = 0; mi < 4; mi++) LDM_X4(ah[mi], aH + mi * (16*AST*2));
        LDM_X4T(r, bH);      bb[0][0]=r[0]; bb[0][1]=r[1]; bb[1][0]=r[2]; bb[1][1]=r[3];
        LDM_X4T(r, bH + 32); bb[2][0]=r[0]; bb[2][1]=r[1]; bb[3][0]=r[2]; bb[3][1]=r[3];
#pragma unroll
        for (int mi = 0; mi < 4; mi++)
#pragma unroll
            for (int ni = 0; ni < 4; ni++) MMA16816(acc[mi][ni], ah[mi], bb[ni]);
#pragma unroll
        for (int mi = 0; mi < 4; mi++) LDM_X4(al[mi], aL + mi * (16*AST*2));
#pragma unroll
        for (int mi = 0; mi < 4; mi++)
#pragma unroll
            for (int ni = 0; ni < 4; ni++) MMA16816(acc[mi][ni], al[mi], bb[ni]);
        LDM_X4T(r, bL);      bb[0][0]=r[0]; bb[0][1]=r[1]; bb[1][0]=r[2]; bb[1][1]=r[3];
        LDM_X4T(r, bL + 32); bb[2][0]=r[0]; bb[2][1]=r[1]; bb[3][0]=r[2]; bb[3][1]=r[3];
#pragma unroll
        for (int mi = 0; mi < 4; mi++)
#pragma unroll
            for (int ni = 0; ni < 4; ni++) MMA16816(acc[mi][ni], ah[mi], bb[ni]);
    };

    // prologue: fill STAGES-1 buffers
#pragma unroll
    for (int s = 0; s < STAGES - 1; s++) {
        load_stage(s, s);
        CP_COMMIT();
    }

#pragma unroll 1
    for (int kt = 0; kt < KTILES; kt++) {
        CP_WAIT2();          // tile kt resident (S-1 groups in flight max)
        __syncthreads();     // all warps done with compute(kt-1)
        if (kt + STAGES - 1 < KTILES)
            load_stage(kt + STAGES - 1, (kt + STAGES - 1) & (STAGES - 1));
        CP_COMMIT();         // keep group counting uniform (empty ok)
        compute(kt & (STAGES - 1));
    }

    // ---------------- epilogue ----------------
#pragma unroll
    for (int ni = 0; ni < 4; ni++) {
        const int n = col0 + wc*32 + ni*8 + (lane & 3) * 2;
        const float b0 = bias[n], b1 = bias[n + 1];
        if (SCATTER) {
            const int which = n / C_;
            const int c0 = n % C_;
            const int h = c0 / D_, d0 = c0 % D_;
            const float sc = (which == 0) ? 0.125f : 1.0f;  // fold 1/sqrt(D)
            __nv_bfloat16* dh = (which == 0) ? g_qh : (which == 1) ? g_kh : g_vh;
            __nv_bfloat16* dl = (which == 0) ? g_ql : (which == 1) ? g_kl : g_vl;
#pragma unroll
            for (int mi = 0; mi < 4; mi++) {
                const int m = row0 + wr*64 + mi*16 + (lane >> 2);
                const int b = m / T_, t = m % T_;
                const size_t bse = (((size_t)(b*H_ + h)) * T_ + t) * D_ + d0;
                store_split2(&dh[bse], &dl[bse],
                             (acc[mi][ni][0] + b0) * sc, (acc[mi][ni][1] + b1) * sc);
                store_split2(&dh[bse + 8*D_], &dl[bse + 8*D_],
                             (acc[mi][ni][2] + b0) * sc, (acc[mi][ni][3] + b1) * sc);
            }
        } else {
#pragma unroll
            for (int mi = 0; mi < 4; mi++) {
                const int m = row0 + wr*64 + mi*16 + (lane >> 2);
                *(float2*)&out[(size_t)m * N + n] =
                    make_float2(acc[mi][ni][0] + b0, acc[mi][ni][1] + b1);
                *(float2*)&out[(size_t)(m + 8) * N + n] =
                    make_float2(acc[mi][ni][2] + b0, acc[mi][ni][3] + b1);
            }
        }
    }
}

// ---------------- tensor-core flash attention, double-buffered K/V -------------
#define ATT_PITCH 72
#define KV_ARR (64*ATT_PITCH*2)     /* 9216 B per array */
#define KV_STG (4*KV_ARR)           /* 36864 B per stage: KH|KL|VH|VL */
#define ATT_SMEM (2*KV_STG)         /* 73728 B */

__global__ __launch_bounds__(256) void attn_mma_kernel()
{
    extern __shared__ char dsm[];
    const uint32_t base = s2u(dsm);
    __nv_bfloat16* smp = (__nv_bfloat16*)dsm;

    const int b = blockIdx.z, h = blockIdx.y;
    const int qt = gridDim.x - 1 - blockIdx.x;   // longest-first
    const int q0 = qt * 128;
    const int tid = threadIdx.x, lane = tid & 31, wid = tid >> 5;
    const size_t hb = ((size_t)(b*H_ + h)) * T_ * D_;

    // ---- stage Q tile (128x64 hi/lo) through smem (stage0 region), frag load --
    {
        const int row = tid >> 1, cg = (tid & 1) * 32;
        const uint4* s4h = (const uint4*)(g_qh + hb + (size_t)(q0+row)*D_ + cg);
        const uint4* s4l = (const uint4*)(g_ql + hb + (size_t)(q0+row)*D_ + cg);
        uint4* d4h = (uint4*)(smp + row*ATT_PITCH + cg);
        uint4* d4l = (uint4*)(smp + 2*64*ATT_PITCH + row*ATT_PITCH + cg);
#pragma unroll
        for (int i = 0; i < 4; i++) { d4h[i] = s4h[i]; d4l[i] = s4l[i]; }
    }
    __syncthreads();

    uint32_t qh[4][4], ql[4][4];
    {
        const int qr = lane & 15, qc = (lane & 16) >> 1;
        const uint32_t baseH = base + (uint32_t)((wid*16 + qr)*ATT_PITCH + qc) * 2;
        const uint32_t baseL = baseH + (uint32_t)(2*64*ATT_PITCH*2);
#pragma unroll
        for (int kk = 0; kk < 4; kk++) {
            LDM_X4(qh[kk], baseH + kk * 32);
            LDM_X4(ql[kk], baseL + kk * 32);
        }
    }
    __syncthreads();

    float o[8][4];
#pragma unroll
    for (int n = 0; n < 8; n++)
#pragma unroll
        for (int r = 0; r < 4; r++) o[n][r] = 0.f;
    float m0 = -1e30f, m1 = -1e30f, l0 = 0.f, l1 = 0.f;

    // fragment addressing (offsets within a stage)
    const int kbrow = (lane & 7) + ((lane & 16) >> 1);
    const int kbcol = (lane & 8);
    const int vrow  = lane & 15;
    const int vcolg = (lane & 16) >> 1;
    const uint32_t kOffH = (uint32_t)(kbrow*ATT_PITCH + kbcol) * 2;
    const uint32_t kOffL = KV_ARR + kOffH;
    const uint32_t vOffH = 2*KV_ARR + (uint32_t)(vrow*ATT_PITCH + vcolg) * 2;
    const uint32_t vOffL = KV_ARR + vOffH;

    // cp.async destination offsets (within a stage)
    const int kvr = tid >> 3, kvc = (tid & 7) * 8;
    const uint32_t dOff = (uint32_t)(kvr*ATT_PITCH + kvc) * 2;
    const uint32_t rstep = 32*ATT_PITCH*2;

    auto load_tile = [&](int k0, int buf) {
        const uint32_t sb = base + buf * KV_STG;
        const size_t g = hb + (size_t)(k0 + kvr)*D_ + kvc;
        cpa16(sb + dOff,                  g_kh + g);
        cpa16(sb + dOff + rstep,          g_kh + g + 32*D_);
        cpa16(sb + KV_ARR + dOff,         g_kl + g);
        cpa16(sb + KV_ARR + dOff + rstep, g_kl + g + 32*D_);
        cpa16(sb + 2*KV_ARR + dOff,         g_vh + g);
        cpa16(sb + 2*KV_ARR + dOff + rstep, g_vh + g + 32*D_);
        cpa16(sb + 3*KV_ARR + dOff,         g_vl + g);
        cpa16(sb + 3*KV_ARR + dOff + rstep, g_vl + g + 32*D_);
    };

    const int row_lo = q0 + wid*16 + (lane >> 2);
    const int ntiles = q0/64 + 2;

    load_tile(0, 0);
    CP_COMMIT();

#pragma unroll 1
    for (int t = 0; t < ntiles; t++) {
        const int k0 = t * 64;
        const uint32_t sb = base + (t & 1) * KV_STG;

        CP_WAIT0();          // tile t resident
        __syncthreads();     // all warps done with tile t-1
        if (t + 1 < ntiles) {
            load_tile(k0 + 64, (t + 1) & 1);   // overlap with compute(t)
            CP_COMMIT();
        }

        // ---- S = Q K^T (3 products) ----
        float s[8][4];
#pragma unroll
        for (int n = 0; n < 8; n++)
#pragma unroll
            for (int r = 0; r < 4; r++) s[n][r] = 0.f;

#pragma unroll
        for (int kk = 0; kk < 4; kk++) {
            uint32_t kf[4][4];
#pragma unroll
            for (int np = 0; np < 4; np++)
                LDM_X4(kf[np], sb + kOffH + (uint32_t)(np*16*ATT_PITCH)*2 + kk*32);
#pragma unroll
            for (int np = 0; np < 4; np++) {
                MMA16816(s[2*np],   qh[kk], kf[np]);
                MMA16816(s[2*np+1], qh[kk], kf[np]+2);
            }
#pragma unroll
            for (int np = 0; np < 4; np++) {
                MMA16816(s[2*np],   ql[kk], kf[np]);
                MMA16816(s[2*np+1], ql[kk], kf[np]+2);
            }
#pragma unroll
            for (int np = 0; np < 4; np++)
                LDM_X4(kf[np], sb + kOffL + (uint32_t)(np*16*ATT_PITCH)*2 + kk*32);
#pragma unroll
            for (int np = 0; np < 4; np++) {
                MMA16816(s[2*np],   qh[kk], kf[np]);
                MMA16816(s[2*np+1], qh[kk], kf[np]+2);
            }
        }

        // ---- causal mask ----
        if (k0 + 64 > q0) {
#pragma unroll
            for (int n = 0; n < 8; n++) {
                const int c = k0 + n*8 + 2*(lane & 3);
                if (c     > row_lo)     s[n][0] = -1e30f;
                if (c + 1 > row_lo)     s[n][1] = -1e30f;
                if (c     > row_lo + 8) s[n][2] = -1e30f;
                if (c + 1 > row_lo + 8) s[n][3] = -1e30f;
            }
        }

        // ---- online softmax ----
        float tm0 = -1e30f, tm1 = -1e30f;
#pragma unroll
        for (int n = 0; n < 8; n++) {
            tm0 = fmaxf(tm0, fmaxf(s[n][0], s[n][1]));
            tm1 = fmaxf(tm1, fmaxf(s[n][2], s[n][3]));
        }
        tm0 = fmaxf(tm0, __shfl_xor_sync(0xffffffff, tm0, 1));
        tm0 = fmaxf(tm0, __shfl_xor_sync(0xffffffff, tm0, 2));
        tm1 = fmaxf(tm1, __shfl_xor_sync(0xffffffff, tm1, 1));
        tm1 = fmaxf(tm1, __shfl_xor_sync(0xffffffff, tm1, 2));

        const float mn0 = fmaxf(m0, tm0), mn1 = fmaxf(m1, tm1);
        const float c0 = __expf(m0 - mn0), c1 = __expf(m1 - mn1);
        m0 = mn0; m1 = mn1;
#pragma unroll
        for (int n = 0; n < 8; n++) {
            o[n][0] *= c0; o[n][1] *= c0; o[n][2] *= c1; o[n][3] *= c1;
        }

        float ls0 = 0.f, ls1 = 0.f;
#pragma unroll
        for (int n = 0; n < 8; n++) {
            s[n][0] = __expf(s[n][0] - m0);
            s[n][1] = __expf(s[n][1] - m0);
            s[n][2] = __expf(s[n][2] - m1);
            s[n][3] = __expf(s[n][3] - m1);
            ls0 += s[n][0] + s[n][1];
            ls1 += s[n][2] + s[n][3];
        }
        ls0 += __shfl_xor_sync(0xffffffff, ls0, 1);
        ls0 += __shfl_xor_sync(0xffffffff, ls0, 2);
        ls1 += __shfl_xor_sync(0xffffffff, ls1, 1);
        ls1 += __shfl_xor_sync(0xffffffff, ls1, 2);
        l0 = l0 * c0 + ls0;
        l1 = l1 * c1 + ls1;

        // ---- pack P to split bf16 a-frags ----
        uint32_t pah[4][4], pal[4][4];
#pragma unroll
        for (int j = 0; j < 4; j++) {
            pah[j][0] = pack_hi(s[2*j][0],   s[2*j][1]);
            pah[j][1] = pack_hi(s[2*j][2],   s[2*j][3]);
            pah[j][2] = pack_hi(s[2*j+1][0], s[2*j+1][1]);
            pah[j][3] = pack_hi(s[2*j+1][2], s[2*j+1][3]);
            pal[j][0] = pack_lo(s[2*j][0],   s[2*j][1]);
            pal[j][1] = pack_lo(s[2*j][2],   s[2*j][3]);
            pal[j][2] = pack_lo(s[2*j+1][0], s[2*j+1][1]);
            pal[j][3] = pack_lo(s[2*j+1][2], s[2*j+1][3]);
        }

        // ---- O += P V (3 products) ----
#pragma unroll
        for (int kk = 0; kk < 4; kk++) {
            uint32_t vf[4][4];
#pragma unroll
            for (int nc = 0; nc < 4; nc++)
                LDM_X4T(vf[nc], sb + vOffH + (uint32_t)(kk*16*ATT_PITCH)*2 + nc*32);
#pragma unroll
            for (int nc = 0; nc < 4; nc++) {
                MMA16816(o[2*nc],   pah[kk], vf[nc]);
                MMA16816(o[2*nc+1], pah[kk], vf[nc]+2);
            }
#pragma unroll
            for (int nc = 0; nc < 4; nc++) {
                MMA16816(o[2*nc],   pal[kk], vf[nc]);
                MMA16816(o[2*nc+1], pal[kk], vf[nc]+2);
            }
#pragma unroll
            for (int nc = 0; nc < 4; nc++)
                LDM_X4T(vf[nc], sb + vOffL + (uint32_t)(kk*16*ATT_PITCH)*2 + nc*32);
#pragma unroll
            for (int nc = 0; nc < 4; nc++) {
                MMA16816(o[2*nc],   pah[kk], vf[nc]);
                MMA16816(o[2*nc+1], pah[kk], vf[nc]+2);
            }
        }
    }

    // ---- epilogue ----
    const float inv0 = 1.f / l0, inv1 = 1.f / l1;
    const int r0 = row_lo, r1 = row_lo + 8;
#pragma unroll
    for (int n = 0; n < 8; n++) {
        const int d = n*8 + 2*(lane & 3);
        const size_t y0 = ((size_t)(b*T_ + r0))*C_ + h*D_ + d;
        const size_t y1 = ((size_t)(b*T_ + r1))*C_ + h*D_ + d;
        store_split2(&g_yh[y0], &g_yl[y0], o[n][0]*inv0, o[n][1]*inv0);
        store_split2(&g_yh[y1], &g_yl[y1], o[n][2]*inv1, o[n][3]*inv1);
    }
}

// -------------------------------------------------------------------------------
extern "C" void kernel_launch(void* const* d_in, const int* in_sizes, int n_in,
                              void* d_out, int out_size)
{
    const float* x      = (const float*)d_in[0];
    const float* w_attn = (const float*)d_in[1];
    const float* b_attn = (const float*)d_in[2];
    const float* w_proj = (const float*)d_in[3];
    const float* b_proj = (const float*)d_in[4];
    float* out = (float*)d_out;

    cudaFuncSetAttribute(gemm_splitbf16<true>,
        cudaFuncAttributeMaxDynamicSharedMemorySize, GEMM_SMEM);
    cudaFuncSetAttribute(gemm_splitbf16<false>,
        cudaFuncAttributeMaxDynamicSharedMemorySize, GEMM_SMEM);
    cudaFuncSetAttribute(attn_mma_kernel,
        cudaFuncAttributeMaxDynamicSharedMemorySize, ATT_SMEM);

    {
        int n4 = M_ * C_ / 4;
        split_bf16_kernel<0><<<(n4 + 255) / 256, 256>>>(x, n4);
    }
    {
        int n4 = C_ * 3 * C_ / 4;
        split_bf16_kernel<1><<<(n4 + 255) / 256, 256>>>(w_attn, n4);
    }
    {
        int n4 = C_ * C_ / 4;
        split_bf16_kernel<2><<<(n4 + 255) / 256, 256>>>(w_proj, n4);
    }

    dim3 g1(3 * C_ / BN, M_ / BM);   // (24, 64)
    gemm_splitbf16<true><<<g1, 256, GEMM_SMEM>>>(b_attn, nullptr, 3 * C_);

    dim3 g2(T_ / 128, H_, B_);       // (16, 16, 4)
    attn_mma_kernel<<<g2, 256, ATT_SMEM>>>();

    dim3 g3(C_ / BN, M_ / BM);       // (8, 64)
    gemm_splitbf16<false><<<g3, 256, GEMM_SMEM>>>(b_proj, out, C_);
}

// round 6
// speedup vs baseline: 3.2367x; 1.0108x over previous
#include <cuda_runtime.h>
#include <cuda_bf16.h>
#include <cstdint>

#define B_ 4
#define T_ 2048
#define C_ 1024
#define H_ 16
#define D_ 64
#define M_ (B_*T_)   /* 8192 */

// ---------------- device scratch ---------------------------------------------
__device__ __nv_bfloat16 g_xh[(size_t)M_*C_];
__device__ __nv_bfloat16 g_xl[(size_t)M_*C_];
__device__ __nv_bfloat16 g_wah[(size_t)C_*3*C_];
__device__ __nv_bfloat16 g_wal[(size_t)C_*3*C_];
__device__ __nv_bfloat16 g_wph[(size_t)C_*C_];
__device__ __nv_bfloat16 g_wpl[(size_t)C_*C_];
__device__ __nv_bfloat16 g_yh[(size_t)M_*C_];
__device__ __nv_bfloat16 g_yl[(size_t)M_*C_];
// q/k/v split bf16, [B,H,T,D]
__device__ __nv_bfloat16 g_qh[(size_t)M_*C_];
__device__ __nv_bfloat16 g_ql[(size_t)M_*C_];
__device__ __nv_bfloat16 g_kh[(size_t)M_*C_];
__device__ __nv_bfloat16 g_kl[(size_t)M_*C_];
__device__ __nv_bfloat16 g_vh[(size_t)M_*C_];
__device__ __nv_bfloat16 g_vl[(size_t)M_*C_];

// ---------------- fp32 -> bf16 hi/lo split ------------------------------------
template<int WHICH>
__global__ void split_bf16_kernel(const float* __restrict__ src, int n4)
{
    __nv_bfloat16* hi = (WHICH == 0) ? g_xh : (WHICH == 1) ? g_wah : g_wph;
    __nv_bfloat16* lo = (WHICH == 0) ? g_xl : (WHICH == 1) ? g_wal : g_wpl;
    int i = blockIdx.x * blockDim.x + threadIdx.x;
    if (i >= n4) return;
    float4 v = ((const float4*)src)[i];
    float s[4] = {v.x, v.y, v.z, v.w};
    uint32_t hp[2], lp[2];
#pragma unroll
    for (int p = 0; p < 2; p++) {
        __nv_bfloat16 h0 = __float2bfloat16(s[2*p]);
        __nv_bfloat16 h1 = __float2bfloat16(s[2*p+1]);
        __nv_bfloat16 l0 = __float2bfloat16(s[2*p]   - __bfloat162float(h0));
        __nv_bfloat16 l1 = __float2bfloat16(s[2*p+1] - __bfloat162float(h1));
        hp[p] = (uint32_t)__bfloat16_as_ushort(h0) |
                ((uint32_t)__bfloat16_as_ushort(h1) << 16);
        lp[p] = (uint32_t)__bfloat16_as_ushort(l0) |
                ((uint32_t)__bfloat16_as_ushort(l1) << 16);
    }
    ((uint2*)hi)[i] = make_uint2(hp[0], hp[1]);
    ((uint2*)lo)[i] = make_uint2(lp[0], lp[1]);
}

// ---------------- helpers ------------------------------------------------------
__device__ __forceinline__ uint32_t s2u(const void* p) {
    return (uint32_t)__cvta_generic_to_shared(p);
}
__device__ __forceinline__ void cpa16(uint32_t dst, const void* src) {
    asm volatile("cp.async.cg.shared.global [%0], [%1], 16;" :: "r"(dst), "l"(src));
}
#define CP_COMMIT() asm volatile("cp.async.commit_group;" ::: "memory")
#define CP_WAIT0()  asm volatile("cp.async.wait_group 0;" ::: "memory")
#define CP_WAIT2()  asm volatile("cp.async.wait_group 2;" ::: "memory")

#define LDM_X4(r, addr) \
    asm volatile("ldmatrix.sync.aligned.m8n8.x4.shared.b16 {%0,%1,%2,%3},[%4];" \
        : "=r"((r)[0]), "=r"((r)[1]), "=r"((r)[2]), "=r"((r)[3]) : "r"(addr))
#define LDM_X4T(r, addr) \
    asm volatile("ldmatrix.sync.aligned.m8n8.x4.trans.shared.b16 {%0,%1,%2,%3},[%4];" \
        : "=r"((r)[0]), "=r"((r)[1]), "=r"((r)[2]), "=r"((r)[3]) : "r"(addr))

#define MMA16816(d, a, b) \
    asm volatile("mma.sync.aligned.m16n8k16.row.col.f32.bf16.bf16.f32 " \
        "{%0,%1,%2,%3},{%4,%5,%6,%7},{%8,%9},{%0,%1,%2,%3};" \
        : "+f"((d)[0]), "+f"((d)[1]), "+f"((d)[2]), "+f"((d)[3]) \
        : "r"((a)[0]), "r"((a)[1]), "r"((a)[2]), "r"((a)[3]), \
          "r"((b)[0]), "r"((b)[1]))

__device__ __forceinline__ void store_split2(
    __nv_bfloat16* ph, __nv_bfloat16* pl, float a, float b)
{
    __nv_bfloat16 ha = __float2bfloat16(a);
    __nv_bfloat16 hb = __float2bfloat16(b);
    __nv_bfloat16 la = __float2bfloat16(a - __bfloat162float(ha));
    __nv_bfloat16 lb = __float2bfloat16(b - __bfloat162float(hb));
    __nv_bfloat162 hv; hv.x = ha; hv.y = hb;
    __nv_bfloat162 lv; lv.x = la; lv.y = lb;
    *(__nv_bfloat162*)ph = hv;
    *(__nv_bfloat162*)pl = lv;
}
__device__ __forceinline__ uint32_t pack_hi(float a, float b) {
    __nv_bfloat162 v; v.x = __float2bfloat16(a); v.y = __float2bfloat16(b);
    return *(uint32_t*)&v;
}
__device__ __forceinline__ uint32_t pack_lo(float a, float b) {
    __nv_bfloat16 ha = __float2bfloat16(a), hb = __float2bfloat16(b);
    __nv_bfloat162 v;
    v.x = __float2bfloat16(a - __bfloat162float(ha));
    v.y = __float2bfloat16(b - __bfloat162float(hb));
    return *(uint32_t*)&v;
}

// ---------------- split-bf16 3-product GEMM, 4-stage pipeline ------------------
#define BM 128
#define BN 128
#define BK 16
#define AST 24    /* A smem row pitch (bf16) */
#define BST 136   /* B smem row pitch (bf16) */
#define KTILES (C_/BK)          /* 64 */
#define STAGES 4
#define ASZ (BM*AST*2)          /* 6144 B per A array */
#define BSZ (BK*BST*2)          /* 4352 B per B array */
#define STG (2*ASZ + 2*BSZ)     /* 20992 B per stage  */
#define GEMM_SMEM (STAGES*STG)  /* 83968 B */

template<bool SCATTER>
__global__ __launch_bounds__(256, 2) void gemm_splitbf16(
    const float* __restrict__ bias, float* __restrict__ out, int N)
{
    extern __shared__ char dsm[];
    const uint32_t base = s2u(dsm);

    const __nv_bfloat16* Agh = SCATTER ? g_xh : g_yh;
    const __nv_bfloat16* Agl = SCATTER ? g_xl : g_yl;
    const __nv_bfloat16* Bgh = SCATTER ? g_wah : g_wph;
    const __nv_bfloat16* Bgl = SCATTER ? g_wal : g_wpl;

    const int K = C_;
    const int tid  = threadIdx.x;
    const int lane = tid & 31, wid = tid >> 5;
    const int wr = wid >> 2, wc = wid & 3;
    const int row0 = blockIdx.y * BM, col0 = blockIdx.x * BN;

    const int rA = tid >> 1, cA = tid & 1;
    const int rB = tid >> 4, cB = tid & 15;

    const __nv_bfloat16* srcAh = Agh + (size_t)(row0 + rA) * K + cA * 8;
    const __nv_bfloat16* srcAl = Agl + (size_t)(row0 + rA) * K + cA * 8;
    const __nv_bfloat16* srcBh = Bgh + (size_t)rB * N + col0 + cB * 8;
    const __nv_bfloat16* srcBl = Bgl + (size_t)rB * N + col0 + cB * 8;

    const uint32_t offA = (uint32_t)(rA*AST + cA*8) * 2;
    const uint32_t offB = (uint32_t)(rB*BST + cB*8) * 2;

    auto load_stage = [&](int kt, int buf) {
        const uint32_t sb = base + buf * STG;
        cpa16(sb + offA,               srcAh + kt * BK);
        cpa16(sb + ASZ + offA,         srcAl + kt * BK);
        cpa16(sb + 2*ASZ + offB,       srcBh + (size_t)kt * BK * N);
        cpa16(sb + 2*ASZ + BSZ + offB, srcBl + (size_t)kt * BK * N);
    };

    const int lm = lane & 15, lh = lane >> 4;
    const uint32_t aOff = (uint32_t)((wr*64 + lm) * AST + lh * 8) * 2;
    const uint32_t bOff = (uint32_t)(lm * BST + (wc*32 + lh*8)) * 2;

    float acc[4][4][4];
#pragma unroll
    for (int mi = 0; mi < 4; mi++)
#pragma unroll
        for (int ni = 0; ni < 4; ni++)
#pragma unroll
            for (int r = 0; r < 4; r++) acc[mi][ni][r] = 0.f;

    // product order: ah*bH -> ah*bL -> al*bH (single LDSM-stall point per tile;
    // al prefetch hides under ah*bL MMAs)
    auto compute = [&](int buf) {
        const uint32_t sb = base + buf * STG;
        const uint32_t aH = sb + aOff;
        const uint32_t aL = sb + ASZ + aOff;
        const uint32_t bH = sb + 2*ASZ + bOff;
        const uint32_t bL = sb + 2*ASZ + BSZ + bOff;
        uint32_t ah[4][4], al[4][4], bbH[4][2], bbL[4][2], r[4];
        // upfront frags: ah, bH, bL
#pragma unroll
        for (int mi = 0; mi < 4; mi++) LDM_X4(ah[mi], aH + mi * (16*AST*2));
        LDM_X4T(r, bH);      bbH[0][0]=r[0]; bbH[0][1]=r[1]; bbH[1][0]=r[2]; bbH[1][1]=r[3];
        LDM_X4T(r, bH + 32); bbH[2][0]=r[0]; bbH[2][1]=r[1]; bbH[3][0]=r[2]; bbH[3][1]=r[3];
        LDM_X4T(r, bL);      bbL[0][0]=r[0]; bbL[0][1]=r[1]; bbL[1][0]=r[2]; bbL[1][1]=r[3];
        LDM_X4T(r, bL + 32); bbL[2][0]=r[0]; bbL[2][1]=r[1]; bbL[3][0]=r[2]; bbL[3][1]=r[3];
        // group 1: ah * bH
#pragma unroll
        for (int mi = 0; mi < 4; mi++)
#pragma unroll
            for (int ni = 0; ni < 4; ni++) MMA16816(acc[mi][ni], ah[mi], bbH[ni]);
        // prefetch al (latency hidden under group 2 MMAs)
#pragma unroll
        for (int mi = 0; mi < 4; mi++) LDM_X4(al[mi], aL + mi * (16*AST*2));
        // group 2: ah * bL (frags already live)
#pragma unroll
        for (int mi = 0; mi < 4; mi++)
#pragma unroll
            for (int ni = 0; ni < 4; ni++) MMA16816(acc[mi][ni], ah[mi], bbL[ni]);
        // group 3: al * bH
#pragma unroll
        for (int mi = 0; mi < 4; mi++)
#pragma unroll
            for (int ni = 0; ni < 4; ni++) MMA16816(acc[mi][ni], al[mi], bbH[ni]);
    };

    // prologue: fill STAGES-1 buffers
#pragma unroll
    for (int s = 0; s < STAGES - 1; s++) {
        load_stage(s, s);
        CP_COMMIT();
    }

#pragma unroll 1
    for (int kt = 0; kt < KTILES; kt++) {
        CP_WAIT2();
        __syncthreads();
        if (kt + STAGES - 1 < KTILES)
            load_stage(kt + STAGES - 1, (kt + STAGES - 1) & (STAGES - 1));
        CP_COMMIT();
        compute(kt & (STAGES - 1));
    }

    // ---------------- epilogue ----------------
#pragma unroll
    for (int ni = 0; ni < 4; ni++) {
        const int n = col0 + wc*32 + ni*8 + (lane & 3) * 2;
        const float b0 = bias[n], b1 = bias[n + 1];
        if (SCATTER) {
            const int which = n / C_;
            const int c0 = n % C_;
            const int h = c0 / D_, d0 = c0 % D_;
            const float sc = (which == 0) ? 0.125f : 1.0f;
            __nv_bfloat16* dh = (which == 0) ? g_qh : (which == 1) ? g_kh : g_vh;
            __nv_bfloat16* dl = (which == 0) ? g_ql : (which == 1) ? g_kl : g_vl;
#pragma unroll
            for (int mi = 0; mi < 4; mi++) {
                const int m = row0 + wr*64 + mi*16 + (lane >> 2);
                const int b = m / T_, t = m % T_;
                const size_t bse = (((size_t)(b*H_ + h)) * T_ + t) * D_ + d0;
                store_split2(&dh[bse], &dl[bse],
                             (acc[mi][ni][0] + b0) * sc, (acc[mi][ni][1] + b1) * sc);
                store_split2(&dh[bse + 8*D_], &dl[bse + 8*D_],
                             (acc[mi][ni][2] + b0) * sc, (acc[mi][ni][3] + b1) * sc);
            }
        } else {
#pragma unroll
            for (int mi = 0; mi < 4; mi++) {
                const int m = row0 + wr*64 + mi*16 + (lane >> 2);
                *(float2*)&out[(size_t)m * N + n] =
                    make_float2(acc[mi][ni][0] + b0, acc[mi][ni][1] + b1);
                *(float2*)&out[(size_t)(m + 8) * N + n] =
                    make_float2(acc[mi][ni][2] + b0, acc[mi][ni][3] + b1);
            }
        }
    }
}

// ---------------- tensor-core flash attention, double-buffered K/V -------------
#define ATT_PITCH 72
#define KV_ARR (64*ATT_PITCH*2)     /* 9216 B per array */
#define KV_STG (4*KV_ARR)           /* 36864 B per stage: KH|KL|VH|VL */
#define ATT_SMEM (2*KV_STG)         /* 73728 B */

__global__ __launch_bounds__(256, 2) void attn_mma_kernel()
{
    extern __shared__ char dsm[];
    const uint32_t base = s2u(dsm);
    __nv_bfloat16* smp = (__nv_bfloat16*)dsm;

    const int b = blockIdx.z, h = blockIdx.y;
    const int qt = gridDim.x - 1 - blockIdx.x;   // longest-first
    const int q0 = qt * 128;
    const int tid = threadIdx.x, lane = tid & 31, wid = tid >> 5;
    const size_t hb = ((size_t)(b*H_ + h)) * T_ * D_;

    // ---- stage Q tile (128x64 hi/lo) through smem, frag load ----
    {
        const int row = tid >> 1, cg = (tid & 1) * 32;
        const uint4* s4h = (const uint4*)(g_qh + hb + (size_t)(q0+row)*D_ + cg);
        const uint4* s4l = (const uint4*)(g_ql + hb + (size_t)(q0+row)*D_ + cg);
        uint4* d4h = (uint4*)(smp + row*ATT_PITCH + cg);
        uint4* d4l = (uint4*)(smp + 2*64*ATT_PITCH + row*ATT_PITCH + cg);
#pragma unroll
        for (int i = 0; i < 4; i++) { d4h[i] = s4h[i]; d4l[i] = s4l[i]; }
    }
    __syncthreads();

    uint32_t qh[4][4], ql[4][4];
    {
        const int qr = lane & 15, qc = (lane & 16) >> 1;
        const uint32_t baseH = base + (uint32_t)((wid*16 + qr)*ATT_PITCH + qc) * 2;
        const uint32_t baseL = baseH + (uint32_t)(2*64*ATT_PITCH*2);
#pragma unroll
        for (int kk = 0; kk < 4; kk++) {
            LDM_X4(qh[kk], baseH + kk * 32);
            LDM_X4(ql[kk], baseL + kk * 32);
        }
    }
    __syncthreads();

    float o[8][4];
#pragma unroll
    for (int n = 0; n < 8; n++)
#pragma unroll
        for (int r = 0; r < 4; r++) o[n][r] = 0.f;
    float m0 = -1e30f, m1 = -1e30f, l0 = 0.f, l1 = 0.f;

    const int kbrow = (lane & 7) + ((lane & 16) >> 1);
    const int kbcol = (lane & 8);
    const int vrow  = lane & 15;
    const int vcolg = (lane & 16) >> 1;
    const uint32_t kOffH = (uint32_t)(kbrow*ATT_PITCH + kbcol) * 2;
    const uint32_t kOffL = KV_ARR + kOffH;
    const uint32_t vOffH = 2*KV_ARR + (uint32_t)(vrow*ATT_PITCH + vcolg) * 2;
    const uint32_t vOffL = KV_ARR + vOffH;

    const int kvr = tid >> 3, kvc = (tid & 7) * 8;
    const uint32_t dOff = (uint32_t)(kvr*ATT_PITCH + kvc) * 2;
    const uint32_t rstep = 32*ATT_PITCH*2;

    auto load_tile = [&](int k0, int buf) {
        const uint32_t sb = base + buf * KV_STG;
        const size_t g = hb + (size_t)(k0 + kvr)*D_ + kvc;
        cpa16(sb + dOff,                  g_kh + g);
        cpa16(sb + dOff + rstep,          g_kh + g + 32*D_);
        cpa16(sb + KV_ARR + dOff,         g_kl + g);
        cpa16(sb + KV_ARR + dOff + rstep, g_kl + g + 32*D_);
        cpa16(sb + 2*KV_ARR + dOff,         g_vh + g);
        cpa16(sb + 2*KV_ARR + dOff + rstep, g_vh + g + 32*D_);
        cpa16(sb + 3*KV_ARR + dOff,         g_vl + g);
        cpa16(sb + 3*KV_ARR + dOff + rstep, g_vl + g + 32*D_);
    };

    const int row_lo = q0 + wid*16 + (lane >> 2);
    const int ntiles = q0/64 + 2;

    load_tile(0, 0);
    CP_COMMIT();

#pragma unroll 1
    for (int t = 0; t < ntiles; t++) {
        const int k0 = t * 64;
        const uint32_t sb = base + (t & 1) * KV_STG;

        CP_WAIT0();
        __syncthreads();
        if (t + 1 < ntiles) {
            load_tile(k0 + 64, (t + 1) & 1);
            CP_COMMIT();
        }

        // ---- S = Q K^T, product order qh*kH -> qh*kL -> ql*kH ----
        float s[8][4];
#pragma unroll
        for (int n = 0; n < 8; n++)
#pragma unroll
            for (int r = 0; r < 4; r++) s[n][r] = 0.f;

#pragma unroll
        for (int kk = 0; kk < 4; kk++) {
            uint32_t kfH[4][4], kfL[4][4];
#pragma unroll
            for (int np = 0; np < 4; np++)
                LDM_X4(kfH[np], sb + kOffH + (uint32_t)(np*16*ATT_PITCH)*2 + kk*32);
            // group 1: qh * kH
#pragma unroll
            for (int np = 0; np < 4; np++) {
                MMA16816(s[2*np],   qh[kk], kfH[np]);
                MMA16816(s[2*np+1], qh[kk], kfH[np]+2);
            }
            // prefetch kL (hidden under group-1 tail / group-2 issue)
#pragma unroll
            for (int np = 0; np < 4; np++)
                LDM_X4(kfL[np], sb + kOffL + (uint32_t)(np*16*ATT_PITCH)*2 + kk*32);
            // group 2: qh * kL
#pragma unroll
            for (int np = 0; np < 4; np++) {
                MMA16816(s[2*np],   qh[kk], kfL[np]);
                MMA16816(s[2*np+1], qh[kk], kfL[np]+2);
            }
            // group 3: ql * kH (kfH still live)
#pragma unroll
            for (int np = 0; np < 4; np++) {
                MMA16816(s[2*np],   ql[kk], kfH[np]);
                MMA16816(s[2*np+1], ql[kk], kfH[np]+2);
            }
        }

        // ---- causal mask ----
        if (k0 + 64 > q0) {
#pragma unroll
            for (int n = 0; n < 8; n++) {
                const int c = k0 + n*8 + 2*(lane & 3);
                if (c     > row_lo)     s[n][0] = -1e30f;
                if (c + 1 > row_lo)     s[n][1] = -1e30f;
                if (c     > row_lo + 8) s[n][2] = -1e30f;
                if (c + 1 > row_lo + 8) s[n][3] = -1e30f;
            }
        }

        // ---- online softmax ----
        float tm0 = -1e30f, tm1 = -1e30f;
#pragma unroll
        for (int n = 0; n < 8; n++) {
            tm0 = fmaxf(tm0, fmaxf(s[n][0], s[n][1]));
            tm1 = fmaxf(tm1, fmaxf(s[n][2], s[n][3]));
        }
        tm0 = fmaxf(tm0, __shfl_xor_sync(0xffffffff, tm0, 1));
        tm0 = fmaxf(tm0, __shfl_xor_sync(0xffffffff, tm0, 2));
        tm1 = fmaxf(tm1, __shfl_xor_sync(0xffffffff, tm1, 1));
        tm1 = fmaxf(tm1, __shfl_xor_sync(0xffffffff, tm1, 2));

        const float mn0 = fmaxf(m0, tm0), mn1 = fmaxf(m1, tm1);
        const float c0 = __expf(m0 - mn0), c1 = __expf(m1 - mn1);
        m0 = mn0; m1 = mn1;
#pragma unroll
        for (int n = 0; n < 8; n++) {
            o[n][0] *= c0; o[n][1] *= c0; o[n][2] *= c1; o[n][3] *= c1;
        }

        float ls0 = 0.f, ls1 = 0.f;
#pragma unroll
        for (int n = 0; n < 8; n++) {
            s[n][0] = __expf(s[n][0] - m0);
            s[n][1] = __expf(s[n][1] - m0);
            s[n][2] = __expf(s[n][2] - m1);
            s[n][3] = __expf(s[n][3] - m1);
            ls0 += s[n][0] + s[n][1];
            ls1 += s[n][2] + s[n][3];
        }
        ls0 += __shfl_xor_sync(0xffffffff, ls0, 1);
        ls0 += __shfl_xor_sync(0xffffffff, ls0, 2);
        ls1 += __shfl_xor_sync(0xffffffff, ls1, 1);
        ls1 += __shfl_xor_sync(0xffffffff, ls1, 2);
        l0 = l0 * c0 + ls0;
        l1 = l1 * c1 + ls1;

        // ---- pack P ----
        uint32_t pah[4][4], pal[4][4];
#pragma unroll
        for (int j = 0; j < 4; j++) {
            pah[j][0] = pack_hi(s[2*j][0],   s[2*j][1]);
            pah[j][1] = pack_hi(s[2*j][2],   s[2*j][3]);
            pah[j][2] = pack_hi(s[2*j+1][0], s[2*j+1][1]);
            pah[j][3] = pack_hi(s[2*j+1][2], s[2*j+1][3]);
            pal[j][0] = pack_lo(s[2*j][0],   s[2*j][1]);
            pal[j][1] = pack_lo(s[2*j][2],   s[2*j][3]);
            pal[j][2] = pack_lo(s[2*j+1][0], s[2*j+1][1]);
            pal[j][3] = pack_lo(s[2*j+1][2], s[2*j+1][3]);
        }

        // ---- O += P V, product order pah*vH -> pah*vL -> pal*vH ----
#pragma unroll
        for (int kk = 0; kk < 4; kk++) {
            uint32_t vfH[4][4], vfL[4][4];
#pragma unroll
            for (int nc = 0; nc < 4; nc++)
                LDM_X4T(vfH[nc], sb + vOffH + (uint32_t)(kk*16*ATT_PITCH)*2 + nc*32);
            // group 1: pah * vH
#pragma unroll
            for (int nc = 0; nc < 4; nc++) {
                MMA16816(o[2*nc],   pah[kk], vfH[nc]);
                MMA16816(o[2*nc+1], pah[kk], vfH[nc]+2);
            }
            // prefetch vL
#pragma unroll
            for (int nc = 0; nc < 4; nc++)
                LDM_X4T(vfL[nc], sb + vOffL + (uint32_t)(kk*16*ATT_PITCH)*2 + nc*32);
            // group 2: pah * vL
#pragma unroll
            for (int nc = 0; nc < 4; nc++) {
                MMA16816(o[2*nc],   pah[kk], vfL[nc]);
                MMA16816(o[2*nc+1], pah[kk], vfL[nc]+2);
            }
            // group 3: pal * vH (vfH still live)
#pragma unroll
            for (int nc = 0; nc < 4; nc++) {
                MMA16816(o[2*nc],   pal[kk], vfH[nc]);
                MMA16816(o[2*nc+1], pal[kk], vfH[nc]+2);
            }
        }
    }

    // ---- epilogue ----
    const float inv0 = 1.f / l0, inv1 = 1.f / l1;
    const int r0 = row_lo, r1 = row_lo + 8;
#pragma unroll
    for (int n = 0; n < 8; n++) {
        const int d = n*8 + 2*(lane & 3);
        const size_t y0 = ((size_t)(b*T_ + r0))*C_ + h*D_ + d;
        const size_t y1 = ((size_t)(b*T_ + r1))*C_ + h*D_ + d;
        store_split2(&g_yh[y0], &g_yl[y0], o[n][0]*inv0, o[n][1]*inv0);
        store_split2(&g_yh[y1], &g_yl[y1], o[n][2]*inv1, o[n][3]*inv1);
    }
}

// -------------------------------------------------------------------------------
extern "C" void kernel_launch(void* const* d_in, const int* in_sizes, int n_in,
                              void* d_out, int out_size)
{
    const float* x      = (const float*)d_in[0];
    const float* w_attn = (const float*)d_in[1];
    const float* b_attn = (const float*)d_in[2];
    const float* w_proj = (const float*)d_in[3];
    const float* b_proj = (const float*)d_in[4];
    float* out = (float*)d_out;

    cudaFuncSetAttribute(gemm_splitbf16<true>,
        cudaFuncAttributeMaxDynamicSharedMemorySize, GEMM_SMEM);
    cudaFuncSetAttribute(gemm_splitbf16<false>,
        cudaFuncAttributeMaxDynamicSharedMemorySize, GEMM_SMEM);
    cudaFuncSetAttribute(attn_mma_kernel,
        cudaFuncAttributeMaxDynamicSharedMemorySize, ATT_SMEM);

    {
        int n4 = M_ * C_ / 4;
        split_bf16_kernel<0><<<(n4 + 255) / 256, 256>>>(x, n4);
    }
    {
        int n4 = C_ * 3 * C_ / 4;
        split_bf16_kernel<1><<<(n4 + 255) / 256, 256>>>(w_attn, n4);
    }
    {
        int n4 = C_ * C_ / 4;
        split_bf16_kernel<2><<<(n4 + 255) / 256, 256>>>(w_proj, n4);
    }

    dim3 g1(3 * C_ / BN, M_ / BM);   // (24, 64)
    gemm_splitbf16<true><<<g1, 256, GEMM_SMEM>>>(b_attn, nullptr, 3 * C_);

    dim3 g2(T_ / 128, H_, B_);       // (16, 16, 4)
    attn_mma_kernel<<<g2, 256, ATT_SMEM>>>();

    dim3 g3(C_ / BN, M_ / BM);       // (8, 64)
    gemm_splitbf16<false><<<g3, 256, GEMM_SMEM>>>(b_proj, out, C_);
}

// round 7
// speedup vs baseline: 4.6039x; 1.4224x over previous
#include <cuda_runtime.h>
#include <cuda_fp16.h>
#include <cstdint>

#define B_ 4
#define T_ 2048
#define C_ 1024
#define H_ 16
#define D_ 64
#define M_ (B_*T_)   /* 8192 */

// ---------------- device scratch (fp16) ----------------------------------------
__device__ __half g_xh[(size_t)M_*C_];
__device__ __half g_xl[(size_t)M_*C_];
__device__ __half g_wa[(size_t)C_*3*C_];   // w_attn single fp16
__device__ __half g_wp[(size_t)C_*C_];     // w_proj single fp16
__device__ __half g_yh[(size_t)M_*C_];
__device__ __half g_yl[(size_t)M_*C_];
// q split (A-operand of S), k/v single, [B,H,T,D]
__device__ __half g_qh[(size_t)M_*C_];
__device__ __half g_ql[(size_t)M_*C_];
__device__ __half g_k[(size_t)M_*C_];
__device__ __half g_v[(size_t)M_*C_];

// ---------------- helpers ------------------------------------------------------
__device__ __forceinline__ uint32_t s2u(const void* p) {
    return (uint32_t)__cvta_generic_to_shared(p);
}
__device__ __forceinline__ void cpa16(uint32_t dst, const void* src) {
    asm volatile("cp.async.cg.shared.global [%0], [%1], 16;" :: "r"(dst), "l"(src));
}
#define CP_COMMIT() asm volatile("cp.async.commit_group;" ::: "memory")
#define CP_WAIT0()  asm volatile("cp.async.wait_group 0;" ::: "memory")
#define CP_WAIT2()  asm volatile("cp.async.wait_group 2;" ::: "memory")

#define LDM_X4(r, addr) \
    asm volatile("ldmatrix.sync.aligned.m8n8.x4.shared.b16 {%0,%1,%2,%3},[%4];" \
        : "=r"((r)[0]), "=r"((r)[1]), "=r"((r)[2]), "=r"((r)[3]) : "r"(addr))
#define LDM_X4T(r, addr) \
    asm volatile("ldmatrix.sync.aligned.m8n8.x4.trans.shared.b16 {%0,%1,%2,%3},[%4];" \
        : "=r"((r)[0]), "=r"((r)[1]), "=r"((r)[2]), "=r"((r)[3]) : "r"(addr))

#define MMA16816(d, a, b) \
    asm volatile("mma.sync.aligned.m16n8k16.row.col.f32.f16.f16.f32 " \
        "{%0,%1,%2,%3},{%4,%5,%6,%7},{%8,%9},{%0,%1,%2,%3};" \
        : "+f"((d)[0]), "+f"((d)[1]), "+f"((d)[2]), "+f"((d)[3]) \
        : "r"((a)[0]), "r"((a)[1]), "r"((a)[2]), "r"((a)[3]), \
          "r"((b)[0]), "r"((b)[1]))

__device__ __forceinline__ uint32_t pack_h2(float a, float b) {
    __half2 v = __floats2half2_rn(a, b);
    return *(uint32_t*)&v;
}
__device__ __forceinline__ uint32_t pack_h2_lo(float a, float b, uint32_t hibits) {
    __half2 h = *(__half2*)&hibits;
    __half2 v;
    v.x = __float2half_rn(a - __half2float(h.x));
    v.y = __float2half_rn(b - __half2float(h.y));
    return *(uint32_t*)&v;
}
__device__ __forceinline__ void store_split2h(
    __half* ph, __half* pl, float a, float b)
{
    uint32_t hi = pack_h2(a, b);
    uint32_t lo = pack_h2_lo(a, b, hi);
    *(uint32_t*)ph = hi;
    *(uint32_t*)pl = lo;
}

// ---------------- fp32 -> fp16 hi/lo split (x) ----------------------------------
__global__ void split_x_kernel(const float* __restrict__ src, int n4)
{
    int i = blockIdx.x * blockDim.x + threadIdx.x;
    if (i >= n4) return;
    float4 v = ((const float4*)src)[i];
    uint32_t h0 = pack_h2(v.x, v.y), h1 = pack_h2(v.z, v.w);
    uint32_t l0 = pack_h2_lo(v.x, v.y, h0), l1 = pack_h2_lo(v.z, v.w, h1);
    ((uint2*)g_xh)[i] = make_uint2(h0, h1);
    ((uint2*)g_xl)[i] = make_uint2(l0, l1);
}

// ---------------- fp32 -> fp16 single convert (weights) -------------------------
template<int WHICH>  // 1: w_attn -> g_wa, 2: w_proj -> g_wp
__global__ void convert_w_kernel(const float* __restrict__ src, int n4)
{
    __half* dst = (WHICH == 1) ? g_wa : g_wp;
    int i = blockIdx.x * blockDim.x + threadIdx.x;
    if (i >= n4) return;
    float4 v = ((const float4*)src)[i];
    ((uint2*)dst)[i] = make_uint2(pack_h2(v.x, v.y), pack_h2(v.z, v.w));
}

// ---------------- split-fp16 2-product GEMM, 4-stage pipeline -------------------
// C = A @ B + bias ; A [M,1024] split fp16 (Ah+Al), B [1024,N] single fp16.
#define BM 128
#define BN 128
#define BK 16
#define AST 24
#define BST 136
#define KTILES (C_/BK)          /* 64 */
#define STAGES 4
#define ASZ (BM*AST*2)          /* 6144 B */
#define BSZ (BK*BST*2)          /* 4352 B */
#define STG (2*ASZ + BSZ)       /* 16640 B per stage */
#define GEMM_SMEM (STAGES*STG)  /* 66560 B */

template<bool SCATTER>
__global__ __launch_bounds__(256, 2) void gemm_splitfp16(
    const float* __restrict__ bias, float* __restrict__ out, int N)
{
    extern __shared__ char dsm[];
    const uint32_t base = s2u(dsm);

    const __half* Agh = SCATTER ? g_xh : g_yh;
    const __half* Agl = SCATTER ? g_xl : g_yl;
    const __half* Bg  = SCATTER ? g_wa : g_wp;

    const int K = C_;
    const int tid  = threadIdx.x;
    const int lane = tid & 31, wid = tid >> 5;
    const int wr = wid >> 2, wc = wid & 3;
    const int row0 = blockIdx.y * BM, col0 = blockIdx.x * BN;

    const int rA = tid >> 1, cA = tid & 1;
    const int rB = tid >> 4, cB = tid & 15;

    const __half* srcAh = Agh + (size_t)(row0 + rA) * K + cA * 8;
    const __half* srcAl = Agl + (size_t)(row0 + rA) * K + cA * 8;
    const __half* srcB  = Bg  + (size_t)rB * N + col0 + cB * 8;

    const uint32_t offA = (uint32_t)(rA*AST + cA*8) * 2;
    const uint32_t offB = (uint32_t)(rB*BST + cB*8) * 2;

    auto load_stage = [&](int kt, int buf) {
        const uint32_t sb = base + buf * STG;
        cpa16(sb + offA,         srcAh + kt * BK);
        cpa16(sb + ASZ + offA,   srcAl + kt * BK);
        cpa16(sb + 2*ASZ + offB, srcB + (size_t)kt * BK * N);
    };

    const int lm = lane & 15, lh = lane >> 4;
    const uint32_t aOff = (uint32_t)((wr*64 + lm) * AST + lh * 8) * 2;
    const uint32_t bOff = (uint32_t)(lm * BST + (wc*32 + lh*8)) * 2;

    float acc[4][4][4];
#pragma unroll
    for (int mi = 0; mi < 4; mi++)
#pragma unroll
        for (int ni = 0; ni < 4; ni++)
#pragma unroll
            for (int r = 0; r < 4; r++) acc[mi][ni][r] = 0.f;

    auto compute = [&](int buf) {
        const uint32_t sb = base + buf * STG;
        const uint32_t aH = sb + aOff;
        const uint32_t aL = sb + ASZ + aOff;
        const uint32_t bB = sb + 2*ASZ + bOff;
        uint32_t ah[4][4], al[4][4], bb[4][2], r[4];
#pragma unroll
        for (int mi = 0; mi < 4; mi++) LDM_X4(ah[mi], aH + mi * (16*AST*2));
        LDM_X4T(r, bB);      bb[0][0]=r[0]; bb[0][1]=r[1]; bb[1][0]=r[2]; bb[1][1]=r[3];
        LDM_X4T(r, bB + 32); bb[2][0]=r[0]; bb[2][1]=r[1]; bb[3][0]=r[2]; bb[3][1]=r[3];
        // group 1: ah * b
#pragma unroll
        for (int mi = 0; mi < 4; mi++)
#pragma unroll
            for (int ni = 0; ni < 4; ni++) MMA16816(acc[mi][ni], ah[mi], bb[ni]);
        // prefetch al, then group 2: al * b
#pragma unroll
        for (int mi = 0; mi < 4; mi++) LDM_X4(al[mi], aL + mi * (16*AST*2));
#pragma unroll
        for (int mi = 0; mi < 4; mi++)
#pragma unroll
            for (int ni = 0; ni < 4; ni++) MMA16816(acc[mi][ni], al[mi], bb[ni]);
    };

#pragma unroll
    for (int s = 0; s < STAGES - 1; s++) {
        load_stage(s, s);
        CP_COMMIT();
    }

#pragma unroll 1
    for (int kt = 0; kt < KTILES; kt++) {
        CP_WAIT2();
        __syncthreads();
        if (kt + STAGES - 1 < KTILES)
            load_stage(kt + STAGES - 1, (kt + STAGES - 1) & (STAGES - 1));
        CP_COMMIT();
        compute(kt & (STAGES - 1));
    }

    // ---------------- epilogue ----------------
#pragma unroll
    for (int ni = 0; ni < 4; ni++) {
        const int n = col0 + wc*32 + ni*8 + (lane & 3) * 2;
        const float b0 = bias[n], b1 = bias[n + 1];
        if (SCATTER) {
            const int which = n / C_;
            const int c0 = n % C_;
            const int h = c0 / D_, d0 = c0 % D_;
#pragma unroll
            for (int mi = 0; mi < 4; mi++) {
                const int m = row0 + wr*64 + mi*16 + (lane >> 2);
                const int b = m / T_, t = m % T_;
                const size_t bse = (((size_t)(b*H_ + h)) * T_ + t) * D_ + d0;
                const float v0 = acc[mi][ni][0] + b0, v1 = acc[mi][ni][1] + b1;
                const float v2 = acc[mi][ni][2] + b0, v3 = acc[mi][ni][3] + b1;
                if (which == 0) {       // q: pre-scale by 1/sqrt(D), split
                    store_split2h(&g_qh[bse], &g_ql[bse], v0 * 0.125f, v1 * 0.125f);
                    store_split2h(&g_qh[bse + 8*D_], &g_ql[bse + 8*D_],
                                  v2 * 0.125f, v3 * 0.125f);
                } else if (which == 1) {  // k: single fp16
                    *(uint32_t*)&g_k[bse]        = pack_h2(v0, v1);
                    *(uint32_t*)&g_k[bse + 8*D_] = pack_h2(v2, v3);
                } else {                  // v: single fp16
                    *(uint32_t*)&g_v[bse]        = pack_h2(v0, v1);
                    *(uint32_t*)&g_v[bse + 8*D_] = pack_h2(v2, v3);
                }
            }
        } else {
#pragma unroll
            for (int mi = 0; mi < 4; mi++) {
                const int m = row0 + wr*64 + mi*16 + (lane >> 2);
                *(float2*)&out[(size_t)m * N + n] =
                    make_float2(acc[mi][ni][0] + b0, acc[mi][ni][1] + b1);
                *(float2*)&out[(size_t)(m + 8) * N + n] =
                    make_float2(acc[mi][ni][2] + b0, acc[mi][ni][3] + b1);
            }
        }
    }
}

// ---------------- fp16 flash attention, double-buffered, 2-product -------------
#define ATT_PITCH 72
#define KV_ARR (64*ATT_PITCH*2)     /* 9216 B per array */
#define KV_STG (2*KV_ARR)           /* 18432 B per stage: K|V */
#define ATT_SMEM (2*KV_STG)         /* 36864 B */

__global__ __launch_bounds__(256, 2) void attn_mma_kernel()
{
    extern __shared__ char dsm[];
    const uint32_t base = s2u(dsm);
    __half* smp = (__half*)dsm;

    const int b = blockIdx.z, h = blockIdx.y;
    const int qt = gridDim.x - 1 - blockIdx.x;   // longest-first
    const int q0 = qt * 128;
    const int tid = threadIdx.x, lane = tid & 31, wid = tid >> 5;
    const size_t hb = ((size_t)(b*H_ + h)) * T_ * D_;

    // ---- stage Q (128x64 hi/lo) through smem (fits in the 2 stages), frag load
    {
        const int row = tid >> 1, cg = (tid & 1) * 32;
        const uint4* s4h = (const uint4*)(g_qh + hb + (size_t)(q0+row)*D_ + cg);
        const uint4* s4l = (const uint4*)(g_ql + hb + (size_t)(q0+row)*D_ + cg);
        uint4* d4h = (uint4*)(smp + row*ATT_PITCH + cg);
        uint4* d4l = (uint4*)(smp + 128*ATT_PITCH + row*ATT_PITCH + cg);
#pragma unroll
        for (int i = 0; i < 4; i++) { d4h[i] = s4h[i]; d4l[i] = s4l[i]; }
    }
    __syncthreads();

    uint32_t qh[4][4], ql[4][4];
    {
        const int qr = lane & 15, qc = (lane & 16) >> 1;
        const uint32_t baseH = base + (uint32_t)((wid*16 + qr)*ATT_PITCH + qc) * 2;
        const uint32_t baseL = baseH + (uint32_t)(128*ATT_PITCH*2);
#pragma unroll
        for (int kk = 0; kk < 4; kk++) {
            LDM_X4(qh[kk], baseH + kk * 32);
            LDM_X4(ql[kk], baseL + kk * 32);
        }
    }
    __syncthreads();

    float o[8][4];
#pragma unroll
    for (int n = 0; n < 8; n++)
#pragma unroll
        for (int r = 0; r < 4; r++) o[n][r] = 0.f;
    float m0 = -1e30f, m1 = -1e30f, l0 = 0.f, l1 = 0.f;

    const int kbrow = (lane & 7) + ((lane & 16) >> 1);
    const int kbcol = (lane & 8);
    const int vrow  = lane & 15;
    const int vcolg = (lane & 16) >> 1;
    const uint32_t kOff = (uint32_t)(kbrow*ATT_PITCH + kbcol) * 2;
    const uint32_t vOff = KV_ARR + (uint32_t)(vrow*ATT_PITCH + vcolg) * 2;

    const int kvr = tid >> 3, kvc = (tid & 7) * 8;
    const uint32_t dOff = (uint32_t)(kvr*ATT_PITCH + kvc) * 2;
    const uint32_t rstep = 32*ATT_PITCH*2;

    auto load_tile = [&](int k0, int buf) {
        const uint32_t sb = base + buf * KV_STG;
        const size_t g = hb + (size_t)(k0 + kvr)*D_ + kvc;
        cpa16(sb + dOff,                  g_k + g);
        cpa16(sb + dOff + rstep,          g_k + g + 32*D_);
        cpa16(sb + KV_ARR + dOff,         g_v + g);
        cpa16(sb + KV_ARR + dOff + rstep, g_v + g + 32*D_);
    };

    const int row_lo = q0 + wid*16 + (lane >> 2);
    const int row_hi_warp = q0 + wid*16 + 15;   // max row this warp owns
    const int ntiles = q0/64 + 2;

    load_tile(0, 0);
    CP_COMMIT();

#pragma unroll 1
    for (int t = 0; t < ntiles; t++) {
        const int k0 = t * 64;
        const uint32_t sb = base + (t & 1) * KV_STG;

        CP_WAIT0();
        __syncthreads();
        if (t + 1 < ntiles) {
            load_tile(k0 + 64, (t + 1) & 1);
            CP_COMMIT();
        }

        // warps whose entire row range is fully masked skip this tile
        if (k0 <= row_hi_warp) {

        // ---- S = Q K^T (qh*k then ql*k) ----
        float s[8][4];
#pragma unroll
        for (int n = 0; n < 8; n++)
#pragma unroll
            for (int r = 0; r < 4; r++) s[n][r] = 0.f;

#pragma unroll
        for (int kk = 0; kk < 4; kk++) {
            uint32_t kf[4][4];
#pragma unroll
            for (int np = 0; np < 4; np++)
                LDM_X4(kf[np], sb + kOff + (uint32_t)(np*16*ATT_PITCH)*2 + kk*32);
#pragma unroll
            for (int np = 0; np < 4; np++) {
                MMA16816(s[2*np],   qh[kk], kf[np]);
                MMA16816(s[2*np+1], qh[kk], kf[np]+2);
            }
#pragma unroll
            for (int np = 0; np < 4; np++) {
                MMA16816(s[2*np],   ql[kk], kf[np]);
                MMA16816(s[2*np+1], ql[kk], kf[np]+2);
            }
        }

        // ---- causal mask ----
        if (k0 + 64 > q0) {
#pragma unroll
            for (int n = 0; n < 8; n++) {
                const int c = k0 + n*8 + 2*(lane & 3);
                if (c     > row_lo)     s[n][0] = -1e30f;
                if (c + 1 > row_lo)     s[n][1] = -1e30f;
                if (c     > row_lo + 8) s[n][2] = -1e30f;
                if (c + 1 > row_lo + 8) s[n][3] = -1e30f;
            }
        }

        // ---- online softmax ----
        float tm0 = -1e30f, tm1 = -1e30f;
#pragma unroll
        for (int n = 0; n < 8; n++) {
            tm0 = fmaxf(tm0, fmaxf(s[n][0], s[n][1]));
            tm1 = fmaxf(tm1, fmaxf(s[n][2], s[n][3]));
        }
        tm0 = fmaxf(tm0, __shfl_xor_sync(0xffffffff, tm0, 1));
        tm0 = fmaxf(tm0, __shfl_xor_sync(0xffffffff, tm0, 2));
        tm1 = fmaxf(tm1, __shfl_xor_sync(0xffffffff, tm1, 1));
        tm1 = fmaxf(tm1, __shfl_xor_sync(0xffffffff, tm1, 2));

        const float mn0 = fmaxf(m0, tm0), mn1 = fmaxf(m1, tm1);
        const float c0 = __expf(m0 - mn0), c1 = __expf(m1 - mn1);
        m0 = mn0; m1 = mn1;
#pragma unroll
        for (int n = 0; n < 8; n++) {
            o[n][0] *= c0; o[n][1] *= c0; o[n][2] *= c1; o[n][3] *= c1;
        }

        float ls0 = 0.f, ls1 = 0.f;
#pragma unroll
        for (int n = 0; n < 8; n++) {
            s[n][0] = __expf(s[n][0] - m0);
            s[n][1] = __expf(s[n][1] - m0);
            s[n][2] = __expf(s[n][2] - m1);
            s[n][3] = __expf(s[n][3] - m1);
            ls0 += s[n][0] + s[n][1];
            ls1 += s[n][2] + s[n][3];
        }
        ls0 += __shfl_xor_sync(0xffffffff, ls0, 1);
        ls0 += __shfl_xor_sync(0xffffffff, ls0, 2);
        ls1 += __shfl_xor_sync(0xffffffff, ls1, 1);
        ls1 += __shfl_xor_sync(0xffffffff, ls1, 2);
        l0 = l0 * c0 + ls0;
        l1 = l1 * c1 + ls1;

        // ---- pack P to split fp16 a-frags ----
        uint32_t pah[4][4], pal[4][4];
#pragma unroll
        for (int j = 0; j < 4; j++) {
            pah[j][0] = pack_h2(s[2*j][0],   s[2*j][1]);
            pah[j][1] = pack_h2(s[2*j][2],   s[2*j][3]);
            pah[j][2] = pack_h2(s[2*j+1][0], s[2*j+1][1]);
            pah[j][3] = pack_h2(s[2*j+1][2], s[2*j+1][3]);
            pal[j][0] = pack_h2_lo(s[2*j][0],   s[2*j][1],   pah[j][0]);
            pal[j][1] = pack_h2_lo(s[2*j][2],   s[2*j][3],   pah[j][1]);
            pal[j][2] = pack_h2_lo(s[2*j+1][0], s[2*j+1][1], pah[j][2]);
            pal[j][3] = pack_h2_lo(s[2*j+1][2], s[2*j+1][3], pah[j][3]);
        }

        // ---- O += P V (pah*v then pal*v) ----
#pragma unroll
        for (int kk = 0; kk < 4; kk++) {
            uint32_t vf[4][4];
#pragma unroll
            for (int nc = 0; nc < 4; nc++)
                LDM_X4T(vf[nc], sb + vOff + (uint32_t)(kk*16*ATT_PITCH)*2 + nc*32);
#pragma unroll
            for (int nc = 0; nc < 4; nc++) {
                MMA16816(o[2*nc],   pah[kk], vf[nc]);
                MMA16816(o[2*nc+1], pah[kk], vf[nc]+2);
            }
#pragma unroll
            for (int nc = 0; nc < 4; nc++) {
                MMA16816(o[2*nc],   pal[kk], vf[nc]);
                MMA16816(o[2*nc+1], pal[kk], vf[nc]+2);
            }
        }

        } // end skip-fully-masked
    }

    // ---- epilogue: y split fp16 ----
    const float inv0 = 1.f / l0, inv1 = 1.f / l1;
    const int r0 = row_lo, r1 = row_lo + 8;
#pragma unroll
    for (int n = 0; n < 8; n++) {
        const int d = n*8 + 2*(lane & 3);
        const size_t y0 = ((size_t)(b*T_ + r0))*C_ + h*D_ + d;
        const size_t y1 = ((size_t)(b*T_ + r1))*C_ + h*D_ + d;
        store_split2h(&g_yh[y0], &g_yl[y0], o[n][0]*inv0, o[n][1]*inv0);
        store_split2h(&g_yh[y1], &g_yl[y1], o[n][2]*inv1, o[n][3]*inv1);
    }
}

// -------------------------------------------------------------------------------
extern "C" void kernel_launch(void* const* d_in, const int* in_sizes, int n_in,
                              void* d_out, int out_size)
{
    const float* x      = (const float*)d_in[0];
    const float* w_attn = (const float*)d_in[1];
    const float* b_attn = (const float*)d_in[2];
    const float* w_proj = (const float*)d_in[3];
    const float* b_proj = (const float*)d_in[4];
    float* out = (float*)d_out;

    cudaFuncSetAttribute(gemm_splitfp16<true>,
        cudaFuncAttributeMaxDynamicSharedMemorySize, GEMM_SMEM);
    cudaFuncSetAttribute(gemm_splitfp16<false>,
        cudaFuncAttributeMaxDynamicSharedMemorySize, GEMM_SMEM);
    cudaFuncSetAttribute(attn_mma_kernel,
        cudaFuncAttributeMaxDynamicSharedMemorySize, ATT_SMEM);

    {
        int n4 = M_ * C_ / 4;
        split_x_kernel<<<(n4 + 255) / 256, 256>>>(x, n4);
    }
    {
        int n4 = C_ * 3 * C_ / 4;
        convert_w_kernel<1><<<(n4 + 255) / 256, 256>>>(w_attn, n4);
    }
    {
        int n4 = C_ * C_ / 4;
        convert_w_kernel<2><<<(n4 + 255) / 256, 256>>>(w_proj, n4);
    }

    dim3 g1(3 * C_ / BN, M_ / BM);   // (24, 64)
    gemm_splitfp16<true><<<g1, 256, GEMM_SMEM>>>(b_attn, nullptr, 3 * C_);

    dim3 g2(T_ / 128, H_, B_);       // (16, 16, 4)
    attn_mma_kernel<<<g2, 256, ATT_SMEM>>>();

    dim3 g3(C_ / BN, M_ / BM);       // (8, 64)
    gemm_splitfp16<false><<<g3, 256, GEMM_SMEM>>>(b_proj, out, C_);
}

// round 8
// speedup vs baseline: 5.2996x; 1.1511x over previous
#include <cuda_runtime.h>
#include <cuda_fp16.h>
#include <cstdint>

#define B_ 4
#define T_ 2048
#define C_ 1024
#define H_ 16
#define D_ 64
#define M_ (B_*T_)   /* 8192 */

// ---------------- device scratch (fp16) ----------------------------------------
__device__ __half g_xh[(size_t)M_*C_];
__device__ __half g_xl[(size_t)M_*C_];
__device__ __half g_wa[(size_t)C_*3*C_];
__device__ __half g_wp[(size_t)C_*C_];
__device__ __half g_yh[(size_t)M_*C_];
__device__ __half g_yl[(size_t)M_*C_];
__device__ __half g_qh[(size_t)M_*C_];
__device__ __half g_ql[(size_t)M_*C_];
__device__ __half g_k[(size_t)M_*C_];
__device__ __half g_v[(size_t)M_*C_];

// ---------------- helpers ------------------------------------------------------
__device__ __forceinline__ uint32_t s2u(const void* p) {
    return (uint32_t)__cvta_generic_to_shared(p);
}
__device__ __forceinline__ void cpa16(uint32_t dst, const void* src) {
    asm volatile("cp.async.cg.shared.global [%0], [%1], 16;" :: "r"(dst), "l"(src));
}
#define CP_COMMIT() asm volatile("cp.async.commit_group;" ::: "memory")
#define CP_WAIT0()  asm volatile("cp.async.wait_group 0;" ::: "memory")
#define CP_WAIT2()  asm volatile("cp.async.wait_group 2;" ::: "memory")

#define LDM_X4(r, addr) \
    asm volatile("ldmatrix.sync.aligned.m8n8.x4.shared.b16 {%0,%1,%2,%3},[%4];" \
        : "=r"((r)[0]), "=r"((r)[1]), "=r"((r)[2]), "=r"((r)[3]) : "r"(addr))
#define LDM_X4T(r, addr) \
    asm volatile("ldmatrix.sync.aligned.m8n8.x4.trans.shared.b16 {%0,%1,%2,%3},[%4];" \
        : "=r"((r)[0]), "=r"((r)[1]), "=r"((r)[2]), "=r"((r)[3]) : "r"(addr))

#define MMA16816(d, a, b) \
    asm volatile("mma.sync.aligned.m16n8k16.row.col.f32.f16.f16.f32 " \
        "{%0,%1,%2,%3},{%4,%5,%6,%7},{%8,%9},{%0,%1,%2,%3};" \
        : "+f"((d)[0]), "+f"((d)[1]), "+f"((d)[2]), "+f"((d)[3]) \
        : "r"((a)[0]), "r"((a)[1]), "r"((a)[2]), "r"((a)[3]), \
          "r"((b)[0]), "r"((b)[1]))

__device__ __forceinline__ float ex2f(float x) {
    float y;
    asm("ex2.approx.f32 %0, %1;" : "=f"(y) : "f"(x));
    return y;
}

__device__ __forceinline__ uint32_t pack_h2(float a, float b) {
    __half2 v = __floats2half2_rn(a, b);
    return *(uint32_t*)&v;
}
__device__ __forceinline__ uint32_t pack_h2_lo(float a, float b, uint32_t hibits) {
    __half2 h = *(__half2*)&hibits;
    __half2 v;
    v.x = __float2half_rn(a - __half2float(h.x));
    v.y = __float2half_rn(b - __half2float(h.y));
    return *(uint32_t*)&v;
}
__device__ __forceinline__ void store_split2h(
    __half* ph, __half* pl, float a, float b)
{
    uint32_t hi = pack_h2(a, b);
    uint32_t lo = pack_h2_lo(a, b, hi);
    *(uint32_t*)ph = hi;
    *(uint32_t*)pl = lo;
}

// q pre-scale: 1/sqrt(D) * log2(e)  (scores land in log2 domain)
#define QSCALE 0.1803368801111306f

// ---------------- fp32 -> fp16 hi/lo split (x) ----------------------------------
__global__ void split_x_kernel(const float* __restrict__ src, int n4)
{
    int i = blockIdx.x * blockDim.x + threadIdx.x;
    if (i >= n4) return;
    float4 v = ((const float4*)src)[i];
    uint32_t h0 = pack_h2(v.x, v.y), h1 = pack_h2(v.z, v.w);
    uint32_t l0 = pack_h2_lo(v.x, v.y, h0), l1 = pack_h2_lo(v.z, v.w, h1);
    ((uint2*)g_xh)[i] = make_uint2(h0, h1);
    ((uint2*)g_xl)[i] = make_uint2(l0, l1);
}

template<int WHICH>
__global__ void convert_w_kernel(const float* __restrict__ src, int n4)
{
    __half* dst = (WHICH == 1) ? g_wa : g_wp;
    int i = blockIdx.x * blockDim.x + threadIdx.x;
    if (i >= n4) return;
    float4 v = ((const float4*)src)[i];
    ((uint2*)dst)[i] = make_uint2(pack_h2(v.x, v.y), pack_h2(v.z, v.w));
}

// ---------------- split-fp16 2-product GEMM, warp grid 4x2 ----------------------
#define BM 128
#define BN 128
#define BK 16
#define AST 24
#define BST 136
#define KTILES (C_/BK)
#define STAGES 4
#define ASZ (BM*AST*2)
#define BSZ (BK*BST*2)
#define STG (2*ASZ + BSZ)
#define GEMM_SMEM (STAGES*STG)

template<bool SCATTER>
__global__ __launch_bounds__(256, 2) void gemm_splitfp16(
    const float* __restrict__ bias, float* __restrict__ out, int N)
{
    extern __shared__ char dsm[];
    const uint32_t base = s2u(dsm);

    const __half* Agh = SCATTER ? g_xh : g_yh;
    const __half* Agl = SCATTER ? g_xl : g_yl;
    const __half* Bg  = SCATTER ? g_wa : g_wp;

    const int K = C_;
    const int tid  = threadIdx.x;
    const int lane = tid & 31, wid = tid >> 5;
    const int wr = wid >> 1, wc = wid & 1;     // 4x2 warp grid: warp tile 32x64
    const int row0 = blockIdx.y * BM, col0 = blockIdx.x * BN;

    const int rA = tid >> 1, cA = tid & 1;
    const int rB = tid >> 4, cB = tid & 15;

    const __half* srcAh = Agh + (size_t)(row0 + rA) * K + cA * 8;
    const __half* srcAl = Agl + (size_t)(row0 + rA) * K + cA * 8;
    const __half* srcB  = Bg  + (size_t)rB * N + col0 + cB * 8;

    const uint32_t offA = (uint32_t)(rA*AST + cA*8) * 2;
    const uint32_t offB = (uint32_t)(rB*BST + cB*8) * 2;

    auto load_stage = [&](int kt, int buf) {
        const uint32_t sb = base + buf * STG;
        cpa16(sb + offA,         srcAh + kt * BK);
        cpa16(sb + ASZ + offA,   srcAl + kt * BK);
        cpa16(sb + 2*ASZ + offB, srcB + (size_t)kt * BK * N);
    };

    const int lm = lane & 15, lh = lane >> 4;
    const uint32_t aOff = (uint32_t)((wr*32 + lm) * AST + lh * 8) * 2;
    const uint32_t bOff = (uint32_t)(lm * BST + (wc*64 + lh*8)) * 2;

    float acc[2][8][4];
#pragma unroll
    for (int mi = 0; mi < 2; mi++)
#pragma unroll
        for (int ni = 0; ni < 8; ni++)
#pragma unroll
            for (int r = 0; r < 4; r++) acc[mi][ni][r] = 0.f;

    auto compute = [&](int buf) {
        const uint32_t sb = base + buf * STG;
        const uint32_t aH = sb + aOff;
        const uint32_t aL = sb + ASZ + aOff;
        const uint32_t bB = sb + 2*ASZ + bOff;
        uint32_t ah[2][4], al[2][4], bb[8][2], r[4];
#pragma unroll
        for (int mi = 0; mi < 2; mi++) LDM_X4(ah[mi], aH + mi * (16*AST*2));
#pragma unroll
        for (int g = 0; g < 4; g++) {
            LDM_X4T(r, bB + g * 32);
            bb[2*g][0]   = r[0]; bb[2*g][1]   = r[1];
            bb[2*g+1][0] = r[2]; bb[2*g+1][1] = r[3];
        }
#pragma unroll
        for (int mi = 0; mi < 2; mi++)
#pragma unroll
            for (int ni = 0; ni < 8; ni++) MMA16816(acc[mi][ni], ah[mi], bb[ni]);
#pragma unroll
        for (int mi = 0; mi < 2; mi++) LDM_X4(al[mi], aL + mi * (16*AST*2));
#pragma unroll
        for (int mi = 0; mi < 2; mi++)
#pragma unroll
            for (int ni = 0; ni < 8; ni++) MMA16816(acc[mi][ni], al[mi], bb[ni]);
    };

#pragma unroll
    for (int s = 0; s < STAGES - 1; s++) {
        load_stage(s, s);
        CP_COMMIT();
    }

#pragma unroll 1
    for (int kt = 0; kt < KTILES; kt++) {
        CP_WAIT2();
        __syncthreads();
        if (kt + STAGES - 1 < KTILES)
            load_stage(kt + STAGES - 1, (kt + STAGES - 1) & (STAGES - 1));
        CP_COMMIT();
        compute(kt & (STAGES - 1));
    }

    // ---------------- epilogue (warp cols span exactly one head) ---------------
    const int ncol0 = col0 + wc * 64;
    const int which = SCATTER ? (ncol0 / C_) : 0;
    const int c0 = ncol0 % C_;
    const int hh = c0 / D_;

#pragma unroll
    for (int ni = 0; ni < 8; ni++) {
        const int n = ncol0 + ni*8 + (lane & 3) * 2;
        const float b0 = bias[n], b1 = bias[n + 1];
        if (SCATTER) {
            const int d0 = (n % C_) % D_;
#pragma unroll
            for (int mi = 0; mi < 2; mi++) {
                const int m = row0 + wr*32 + mi*16 + (lane >> 2);
                const int b = m / T_, t = m % T_;
                const size_t bse = (((size_t)(b*H_ + hh)) * T_ + t) * D_ + d0;
                const float v0 = acc[mi][ni][0] + b0, v1 = acc[mi][ni][1] + b1;
                const float v2 = acc[mi][ni][2] + b0, v3 = acc[mi][ni][3] + b1;
                if (which == 0) {
                    store_split2h(&g_qh[bse], &g_ql[bse], v0 * QSCALE, v1 * QSCALE);
                    store_split2h(&g_qh[bse + 8*D_], &g_ql[bse + 8*D_],
                                  v2 * QSCALE, v3 * QSCALE);
                } else if (which == 1) {
                    *(uint32_t*)&g_k[bse]        = pack_h2(v0, v1);
                    *(uint32_t*)&g_k[bse + 8*D_] = pack_h2(v2, v3);
                } else {
                    *(uint32_t*)&g_v[bse]        = pack_h2(v0, v1);
                    *(uint32_t*)&g_v[bse + 8*D_] = pack_h2(v2, v3);
                }
            }
        } else {
#pragma unroll
            for (int mi = 0; mi < 2; mi++) {
                const int m = row0 + wr*32 + mi*16 + (lane >> 2);
                *(float2*)&out[(size_t)m * N + n] =
                    make_float2(acc[mi][ni][0] + b0, acc[mi][ni][1] + b1);
                *(float2*)&out[(size_t)(m + 8) * N + n] =
                    make_float2(acc[mi][ni][2] + b0, acc[mi][ni][3] + b1);
            }
        }
    }
}

// ---------------- fp16 flash attention, double-buffered, 2-product, ex2 --------
#define ATT_PITCH 72
#define KV_ARR (64*ATT_PITCH*2)
#define KV_STG (2*KV_ARR)
#define ATT_SMEM (2*KV_STG)

__global__ __launch_bounds__(256, 2) void attn_mma_kernel()
{
    extern __shared__ char dsm[];
    const uint32_t base = s2u(dsm);
    __half* smp = (__half*)dsm;

    const int b = blockIdx.z, h = blockIdx.y;
    const int qt = gridDim.x - 1 - blockIdx.x;
    const int q0 = qt * 128;
    const int tid = threadIdx.x, lane = tid & 31, wid = tid >> 5;
    const size_t hb = ((size_t)(b*H_ + h)) * T_ * D_;

    {
        const int row = tid >> 1, cg = (tid & 1) * 32;
        const uint4* s4h = (const uint4*)(g_qh + hb + (size_t)(q0+row)*D_ + cg);
        const uint4* s4l = (const uint4*)(g_ql + hb + (size_t)(q0+row)*D_ + cg);
        uint4* d4h = (uint4*)(smp + row*ATT_PITCH + cg);
        uint4* d4l = (uint4*)(smp + 128*ATT_PITCH + row*ATT_PITCH + cg);
#pragma unroll
        for (int i = 0; i < 4; i++) { d4h[i] = s4h[i]; d4l[i] = s4l[i]; }
    }
    __syncthreads();

    uint32_t qh[4][4], ql[4][4];
    {
        const int qr = lane & 15, qc = (lane & 16) >> 1;
        const uint32_t baseH = base + (uint32_t)((wid*16 + qr)*ATT_PITCH + qc) * 2;
        const uint32_t baseL = baseH + (uint32_t)(128*ATT_PITCH*2);
#pragma unroll
        for (int kk = 0; kk < 4; kk++) {
            LDM_X4(qh[kk], baseH + kk * 32);
            LDM_X4(ql[kk], baseL + kk * 32);
        }
    }
    __syncthreads();

    float o[8][4];
#pragma unroll
    for (int n = 0; n < 8; n++)
#pragma unroll
        for (int r = 0; r < 4; r++) o[n][r] = 0.f;
    float m0 = -1e30f, m1 = -1e30f, l0 = 0.f, l1 = 0.f;

    const int kbrow = (lane & 7) + ((lane & 16) >> 1);
    const int kbcol = (lane & 8);
    const int vrow  = lane & 15;
    const int vcolg = (lane & 16) >> 1;
    const uint32_t kOff = (uint32_t)(kbrow*ATT_PITCH + kbcol) * 2;
    const uint32_t vOff = KV_ARR + (uint32_t)(vrow*ATT_PITCH + vcolg) * 2;

    const int kvr = tid >> 3, kvc = (tid & 7) * 8;
    const uint32_t dOff = (uint32_t)(kvr*ATT_PITCH + kvc) * 2;
    const uint32_t rstep = 32*ATT_PITCH*2;

    auto load_tile = [&](int k0, int buf) {
        const uint32_t sb = base + buf * KV_STG;
        const size_t g = hb + (size_t)(k0 + kvr)*D_ + kvc;
        cpa16(sb + dOff,                  g_k + g);
        cpa16(sb + dOff + rstep,          g_k + g + 32*D_);
        cpa16(sb + KV_ARR + dOff,         g_v + g);
        cpa16(sb + KV_ARR + dOff + rstep, g_v + g + 32*D_);
    };

    const int row_lo = q0 + wid*16 + (lane >> 2);
    const int row_hi_warp = q0 + wid*16 + 15;
    const int ntiles = q0/64 + 2;

    load_tile(0, 0);
    CP_COMMIT();

#pragma unroll 1
    for (int t = 0; t < ntiles; t++) {
        const int k0 = t * 64;
        const uint32_t sb = base + (t & 1) * KV_STG;

        CP_WAIT0();
        __syncthreads();
        if (t + 1 < ntiles) {
            load_tile(k0 + 64, (t + 1) & 1);
            CP_COMMIT();
        }

        if (k0 <= row_hi_warp) {

        float s[8][4];
#pragma unroll
        for (int n = 0; n < 8; n++)
#pragma unroll
            for (int r = 0; r < 4; r++) s[n][r] = 0.f;

#pragma unroll
        for (int kk = 0; kk < 4; kk++) {
            uint32_t kf[4][4];
#pragma unroll
            for (int np = 0; np < 4; np++)
                LDM_X4(kf[np], sb + kOff + (uint32_t)(np*16*ATT_PITCH)*2 + kk*32);
#pragma unroll
            for (int np = 0; np < 4; np++) {
                MMA16816(s[2*np],   qh[kk], kf[np]);
                MMA16816(s[2*np+1], qh[kk], kf[np]+2);
            }
#pragma unroll
            for (int np = 0; np < 4; np++) {
                MMA16816(s[2*np],   ql[kk], kf[np]);
                MMA16816(s[2*np+1], ql[kk], kf[np]+2);
            }
        }

        if (k0 + 64 > q0) {
#pragma unroll
            for (int n = 0; n < 8; n++) {
                const int c = k0 + n*8 + 2*(lane & 3);
                if (c     > row_lo)     s[n][0] = -1e30f;
                if (c + 1 > row_lo)     s[n][1] = -1e30f;
                if (c     > row_lo + 8) s[n][2] = -1e30f;
                if (c + 1 > row_lo + 8) s[n][3] = -1e30f;
            }
        }

        float tm0 = -1e30f, tm1 = -1e30f;
#pragma unroll
        for (int n = 0; n < 8; n++) {
            tm0 = fmaxf(tm0, fmaxf(s[n][0], s[n][1]));
            tm1 = fmaxf(tm1, fmaxf(s[n][2], s[n][3]));
        }
        tm0 = fmaxf(tm0, __shfl_xor_sync(0xffffffff, tm0, 1));
        tm0 = fmaxf(tm0, __shfl_xor_sync(0xffffffff, tm0, 2));
        tm1 = fmaxf(tm1, __shfl_xor_sync(0xffffffff, tm1, 1));
        tm1 = fmaxf(tm1, __shfl_xor_sync(0xffffffff, tm1, 2));

        const float mn0 = fmaxf(m0, tm0), mn1 = fmaxf(m1, tm1);
        const float c0 = ex2f(m0 - mn0), c1 = ex2f(m1 - mn1);
        m0 = mn0; m1 = mn1;
#pragma unroll
        for (int n = 0; n < 8; n++) {
            o[n][0] *= c0; o[n][1] *= c0; o[n][2] *= c1; o[n][3] *= c1;
        }

        float ls0 = 0.f, ls1 = 0.f;
#pragma unroll
        for (int n = 0; n < 8; n++) {
            s[n][0] = ex2f(s[n][0] - m0);
            s[n][1] = ex2f(s[n][1] - m0);
            s[n][2] = ex2f(s[n][2] - m1);
            s[n][3] = ex2f(s[n][3] - m1);
            ls0 += s[n][0] + s[n][1];
            ls1 += s[n][2] + s[n][3];
        }
        ls0 += __shfl_xor_sync(0xffffffff, ls0, 1);
        ls0 += __shfl_xor_sync(0xffffffff, ls0, 2);
        ls1 += __shfl_xor_sync(0xffffffff, ls1, 1);
        ls1 += __shfl_xor_sync(0xffffffff, ls1, 2);
        l0 = l0 * c0 + ls0;
        l1 = l1 * c1 + ls1;

        uint32_t pah[4][4], pal[4][4];
#pragma unroll
        for (int j = 0; j < 4; j++) {
            pah[j][0] = pack_h2(s[2*j][0],   s[2*j][1]);
            pah[j][1] = pack_h2(s[2*j][2],   s[2*j][3]);
            pah[j][2] = pack_h2(s[2*j+1][0], s[2*j+1][1]);
            pah[j][3] = pack_h2(s[2*j+1][2], s[2*j+1][3]);
            pal[j][0] = pack_h2_lo(s[2*j][0],   s[2*j][1],   pah[j][0]);
            pal[j][1] = pack_h2_lo(s[2*j][2],   s[2*j][3],   pah[j][1]);
            pal[j][2] = pack_h2_lo(s[2*j+1][0], s[2*j+1][1], pah[j][2]);
            pal[j][3] = pack_h2_lo(s[2*j+1][2], s[2*j+1][3], pah[j][3]);
        }

#pragma unroll
        for (int kk = 0; kk < 4; kk++) {
            uint32_t vf[4][4];
#pragma unroll
            for (int nc = 0; nc < 4; nc++)
                LDM_X4T(vf[nc], sb + vOff + (uint32_t)(kk*16*ATT_PITCH)*2 + nc*32);
#pragma unroll
            for (int nc = 0; nc < 4; nc++) {
                MMA16816(o[2*nc],   pah[kk], vf[nc]);
                MMA16816(o[2*nc+1], pah[kk], vf[nc]+2);
            }
#pragma unroll
            for (int nc = 0; nc < 4; nc++) {
                MMA16816(o[2*nc],   pal[kk], vf[nc]);
                MMA16816(o[2*nc+1], pal[kk], vf[nc]+2);
            }
        }

        }
    }

    const float inv0 = 1.f / l0, inv1 = 1.f / l1;
    const int r0 = row_lo, r1 = row_lo + 8;
#pragma unroll
    for (int n = 0; n < 8; n++) {
        const int d = n*8 + 2*(lane & 3);
        const size_t y0 = ((size_t)(b*T_ + r0))*C_ + h*D_ + d;
        const size_t y1 = ((size_t)(b*T_ + r1))*C_ + h*D_ + d;
        store_split2h(&g_yh[y0], &g_yl[y0], o[n][0]*inv0, o[n][1]*inv0);
        store_split2h(&g_yh[y1], &g_yl[y1], o[n][2]*inv1, o[n][3]*inv1);
    }
}

// -------------------------------------------------------------------------------
extern "C" void kernel_launch(void* const* d_in, const int* in_sizes, int n_in,
                              void* d_out, int out_size)
{
    const float* x      = (const float*)d_in[0];
    const float* w_attn = (const float*)d_in[1];
    const float* b_attn = (const float*)d_in[2];
    const float* w_proj = (const float*)d_in[3];
    const float* b_proj = (const float*)d_in[4];
    float* out = (float*)d_out;

    cudaFuncSetAttribute(gemm_splitfp16<true>,
        cudaFuncAttributeMaxDynamicSharedMemorySize, GEMM_SMEM);
    cudaFuncSetAttribute(gemm_splitfp16<false>,
        cudaFuncAttributeMaxDynamicSharedMemorySize, GEMM_SMEM);
    cudaFuncSetAttribute(attn_mma_kernel,
        cudaFuncAttributeMaxDynamicSharedMemorySize, ATT_SMEM);

    {
        int n4 = M_ * C_ / 4;
        split_x_kernel<<<(n4 + 255) / 256, 256>>>(x, n4);
    }
    {
        int n4 = C_ * 3 * C_ / 4;
        convert_w_kernel<1><<<(n4 + 255) / 256, 256>>>(w_attn, n4);
    }
    {
        int n4 = C_ * C_ / 4;
        convert_w_kernel<2><<<(n4 + 255) / 256, 256>>>(w_proj, n4);
    }

    dim3 g1(3 * C_ / BN, M_ / BM);   // (24, 64)
    gemm_splitfp16<true><<<g1, 256, GEMM_SMEM>>>(b_attn, nullptr, 3 * C_);

    dim3 g2(T_ / 128, H_, B_);       // (16, 16, 4)
    attn_mma_kernel<<<g2, 256, ATT_SMEM>>>();

    dim3 g3(C_ / BN, M_ / BM);       // (8, 64)
    gemm_splitfp16<false><<<g3, 256, GEMM_SMEM>>>(b_proj, out, C_);
}